// round 13
// baseline (speedup 1.0000x reference)
#include <cuda_runtime.h>
#include <cuda_fp16.h>
#include <cstdint>

#define NN 50000
#define EE 500000
#define NG  128

#define CDIV(a,b) (((a)+(b)-1)/(b))
#define SCAN_NBLK CDIV(NN, 256)      // 196

// ---------------- device scratch (no allocation allowed) ----------------
__device__ __align__(16) float  g_dinv[NN];
__device__ __align__(16) float  g_Y0[NN * 128];     // fp32 accumulator region (max G=128)
__device__ __align__(16) __half g_Vh[NN * 256];     // [V | V2] fp16, ld = 2*G (max 256)
__device__ __align__(16) float  g_H1[NN * 128];
__device__ __align__(16) float  g_H2[NN * 64];
__device__ __align__(16) float  g_Wc1[160 * 384];
__device__ __align__(16) float  g_Wc2[128 * 192];
__device__ __align__(16) float  g_Wc3[64 * 96];
__device__ __align__(16) float  g_pool[NG * 32];
__device__ __align__(16) float  g_cnt[NG];
// CSR (indexed by dst)
__device__ int   g_rowptr[NN + 1];
__device__ int   g_fill[NN];
__device__ int   g_bsum[SCAN_NBLK];
__device__ __align__(16) int   g_csr_src[EE];
__device__ __align__(16) float g_csr_w[EE];

// ---------------- helpers ----------------
__device__ __forceinline__ void red_add_v4(float* addr, float4 v) {
    asm volatile("red.global.add.v4.f32 [%0], {%1,%2,%3,%4};"
                 :: "l"(addr), "f"(v.x), "f"(v.y), "f"(v.z), "f"(v.w)
                 : "memory");
}

__device__ __forceinline__ void mma_f16(float* c, const uint32_t* a, const uint32_t* b) {
    asm volatile("mma.sync.aligned.m16n8k16.row.col.f32.f16.f16.f32 "
                 "{%0,%1,%2,%3}, {%4,%5,%6,%7}, {%8,%9}, {%0,%1,%2,%3};"
                 : "+f"(c[0]), "+f"(c[1]), "+f"(c[2]), "+f"(c[3])
                 : "r"(a[0]), "r"(a[1]), "r"(a[2]), "r"(a[3]),
                   "r"(b[0]), "r"(b[1]));
}

// fp32 -> (hi, lo) fp16 split: x ≈ hi + lo with ~2^-22 combined precision
__device__ __forceinline__ void split_h(float x, __half& hi, __half& lo) {
    hi = __float2half_rn(x);
    lo = __float2half_rn(x - __half2float(hi));
}

// 8 halfs (uint4) -> 8 floats
__device__ __forceinline__ void h8_to_f8(uint4 u, float* f) {
    __half2 a = *(__half2*)&u.x;
    __half2 b = *(__half2*)&u.y;
    __half2 c = *(__half2*)&u.z;
    __half2 d = *(__half2*)&u.w;
    float2 fa = __half22float2(a), fb = __half22float2(b);
    float2 fc = __half22float2(c), fd = __half22float2(d);
    f[0] = fa.x; f[1] = fa.y; f[2] = fb.x; f[3] = fb.y;
    f[4] = fc.x; f[5] = fc.y; f[6] = fd.x; f[7] = fd.y;
}

__device__ __forceinline__ uint4 f8_to_h8(const float* f) {
    __half2 a = __floats2half2_rn(f[0], f[1]);
    __half2 b = __floats2half2_rn(f[2], f[3]);
    __half2 c = __floats2half2_rn(f[4], f[5]);
    __half2 d = __floats2half2_rn(f[6], f[7]);
    uint4 u;
    u.x = *(uint32_t*)&a; u.y = *(uint32_t*)&b;
    u.z = *(uint32_t*)&c; u.w = *(uint32_t*)&d;
    return u;
}

// ---------------- fused preamble kernels ----------------
__global__ void zero_all_kernel() {
    int i = blockIdx.x * blockDim.x + threadIdx.x;
    if (i < NN) { g_dinv[i] = 0.f; g_fill[i] = 0; }
    if (i < NG * 32) g_pool[i] = 0.f;
    if (i < NG) g_cnt[i] = 0.f;
}

// 4 edges / thread: degree accumulation + CSR row counting + per-graph node counts
__global__ void deg_count_kernel(const int* __restrict__ src, const int* __restrict__ dst,
                                 const float* __restrict__ ea, const int* __restrict__ batch) {
    int t = blockIdx.x * blockDim.x + threadIdx.x;
    if (t < EE / 4) {
        int4  s4 = ((const int4*)src)[t];
        int4  d4 = ((const int4*)dst)[t];
        float4 a4 = ((const float4*)ea)[t];
        atomicAdd(&g_dinv[s4.x], a4.x);
        atomicAdd(&g_dinv[s4.y], a4.y);
        atomicAdd(&g_dinv[s4.z], a4.z);
        atomicAdd(&g_dinv[s4.w], a4.w);
        atomicAdd(&g_fill[d4.x], 1);
        atomicAdd(&g_fill[d4.y], 1);
        atomicAdd(&g_fill[d4.z], 1);
        atomicAdd(&g_fill[d4.w], 1);
    }
    if (t < NN / 4) {
        int4 b4 = ((const int4*)batch)[t];
        atomicAdd(&g_cnt[b4.x], 1.0f);
        atomicAdd(&g_cnt[b4.y], 1.0f);
        atomicAdd(&g_cnt[b4.z], 1.0f);
        atomicAdd(&g_cnt[b4.w], 1.0f);
    }
}

// ---------------- multi-block scan of g_fill -> g_rowptr ----------------
__global__ void scan_phase1_kernel() {
    __shared__ int sh[256];
    int tid = threadIdx.x;
    int i = blockIdx.x * 256 + tid;
    int c = (i < NN) ? g_fill[i] : 0;
    if (i < NN) {
        float d = g_dinv[i];
        g_dinv[i] = (d > 0.f) ? rsqrtf(d) : 0.f;
    }
    int v = c;
    sh[tid] = v;
    __syncthreads();
#pragma unroll
    for (int off = 1; off < 256; off <<= 1) {
        int t = (tid >= off) ? sh[tid - off] : 0;
        __syncthreads();
        v += t;
        sh[tid] = v;
        __syncthreads();
    }
    if (i < NN) g_rowptr[i] = v - c;
    if (tid == 255) g_bsum[blockIdx.x] = sh[255];
}

__global__ void scan_phase23_kernel() {
    __shared__ int sh[256];
    int tid = threadIdx.x;
    int c = (tid < SCAN_NBLK) ? g_bsum[tid] : 0;
    int v = c;
    sh[tid] = v;
    __syncthreads();
#pragma unroll
    for (int off = 1; off < 256; off <<= 1) {
        int t = (tid >= off) ? sh[tid - off] : 0;
        __syncthreads();
        v += t;
        sh[tid] = v;
        __syncthreads();
    }
    int boff = (blockIdx.x > 0) ? sh[blockIdx.x - 1] : 0;
    __syncthreads();
    int i = blockIdx.x * 256 + tid;
    if (i < NN) {
        int r = g_rowptr[i] + boff;
        g_rowptr[i] = r;
        g_fill[i] = r;
    }
    if (i == 0) g_rowptr[NN] = EE;
}

// 4 edges / thread: scatter into CSR with normalized weight computed inline
__global__ void scatter_w_kernel(const int* __restrict__ src, const int* __restrict__ dst,
                                 const float* __restrict__ ea) {
    int t = blockIdx.x * blockDim.x + threadIdx.x;
    if (t >= EE / 4) return;
    int4  s4 = ((const int4*)src)[t];
    int4  d4 = ((const int4*)dst)[t];
    float4 a4 = ((const float4*)ea)[t];

    float w0 = -g_dinv[s4.x] * a4.x * g_dinv[d4.x];
    float w1 = -g_dinv[s4.y] * a4.y * g_dinv[d4.y];
    float w2 = -g_dinv[s4.z] * a4.z * g_dinv[d4.z];
    float w3 = -g_dinv[s4.w] * a4.w * g_dinv[d4.w];

    int p0 = atomicAdd(&g_fill[d4.x], 1);
    int p1 = atomicAdd(&g_fill[d4.y], 1);
    int p2 = atomicAdd(&g_fill[d4.z], 1);
    int p3 = atomicAdd(&g_fill[d4.w], 1);

    g_csr_src[p0] = s4.x; g_csr_w[p0] = w0;
    g_csr_src[p1] = s4.y; g_csr_w[p1] = w1;
    g_csr_src[p2] = s4.z; g_csr_w[p2] = w2;
    g_csr_src[p3] = s4.w; g_csr_w[p3] = w3;
}

// ---------------- weight prep for all 3 layers: Wc[f] = [W0-W2 | W1 | 2*W2] ---------
__device__ __forceinline__ void wprep_one(const float* __restrict__ W, float* __restrict__ Wc,
                                          int F, int G, int t) {
    int f = t / G;
    int c = t - f * G;
    float w0 = W[t];
    float w1 = W[F * G + t];
    float w2 = W[2 * F * G + t];
    Wc[f * 3 * G + c]         = w0 - w2;
    Wc[f * 3 * G + G + c]     = w1;
    Wc[f * 3 * G + 2 * G + c] = 2.f * w2;
}

__global__ void wprep_all_kernel(const float* __restrict__ W1, const float* __restrict__ W2,
                                 const float* __restrict__ W3) {
    int t = blockIdx.x * blockDim.x + threadIdx.x;
    const int S1 = 160 * 128, S2 = S1 + 128 * 64, S3 = S2 + 64 * 32;
    if (t < S1)      wprep_one(W1, g_Wc1, 160, 128, t);
    else if (t < S2) wprep_one(W2, g_Wc2, 128, 64, t - S1);
    else if (t < S3) wprep_one(W3, g_Wc3, 64, 32, t - S2);
}

// ---------------- CSR gather propagate (fp16, 16B lanes) ----------------
// Vh per node: 2G halfs = G/4 uint4; V region uint4 [0, G/8), V2 region [G/8, G/4)
// MODE 0: Vh.V[n]  = Vh.V[n] + sum_e w * Vh.V2[src]       (Z = V + P V2)
// MODE 1: H[n]     = relu(Y0[n] + sum_e w * Vh.V[src] + b)
// MODE 2: pool[batch[n]] += relu(...)                      (layer-3 fused pooling)
template <int G, int MODE>
__global__ void gather_kernel(float* __restrict__ H,
                              const float* __restrict__ bias,
                              const int* __restrict__ batch) {
    const int LPN = G / 8;
    const int LDH = G / 4;
    int tid = blockIdx.x * blockDim.x + threadIdx.x;
    int node = tid / LPN;
    int lane = tid % LPN;
    if (node >= NN) return;

    uint4* vh4 = (uint4*)g_Vh;
    int beg = g_rowptr[node];
    int end = g_rowptr[node + 1];

    const int srcoff = (MODE == 0) ? LPN : 0;
    float acc[8];
    if (MODE == 0) {
        h8_to_f8(vh4[(size_t)node * LDH + lane], acc);
    } else {
        float4 lo = ((const float4*)g_Y0)[(size_t)node * (G / 4) + lane * 2];
        float4 hi = ((const float4*)g_Y0)[(size_t)node * (G / 4) + lane * 2 + 1];
        acc[0] = lo.x; acc[1] = lo.y; acc[2] = lo.z; acc[3] = lo.w;
        acc[4] = hi.x; acc[5] = hi.y; acc[6] = hi.z; acc[7] = hi.w;
    }

    int j = beg;
    for (; j + 3 < end; j += 4) {
        int s[4]; float w[4]; uint4 v[4];
#pragma unroll
        for (int u = 0; u < 4; ++u) { s[u] = g_csr_src[j + u]; w[u] = g_csr_w[j + u]; }
#pragma unroll
        for (int u = 0; u < 4; ++u) v[u] = vh4[(size_t)s[u] * LDH + srcoff + lane];
#pragma unroll
        for (int u = 0; u < 4; ++u) {
            float f[8];
            h8_to_f8(v[u], f);
#pragma unroll
            for (int r = 0; r < 8; ++r) acc[r] = fmaf(w[u], f[r], acc[r]);
        }
    }
    for (; j < end; ++j) {
        int s0 = g_csr_src[j];
        float w0 = g_csr_w[j];
        float f[8];
        h8_to_f8(vh4[(size_t)s0 * LDH + srcoff + lane], f);
#pragma unroll
        for (int r = 0; r < 8; ++r) acc[r] = fmaf(w0, f[r], acc[r]);
    }

    if (MODE == 0) {
        vh4[(size_t)node * LDH + lane] = f8_to_h8(acc);
    } else {
        float4 blo = ((const float4*)bias)[lane * 2];
        float4 bhi = ((const float4*)bias)[lane * 2 + 1];
        float4 olo, ohi;
        olo.x = fmaxf(acc[0] + blo.x, 0.f);
        olo.y = fmaxf(acc[1] + blo.y, 0.f);
        olo.z = fmaxf(acc[2] + blo.z, 0.f);
        olo.w = fmaxf(acc[3] + blo.w, 0.f);
        ohi.x = fmaxf(acc[4] + bhi.x, 0.f);
        ohi.y = fmaxf(acc[5] + bhi.y, 0.f);
        ohi.z = fmaxf(acc[6] + bhi.z, 0.f);
        ohi.w = fmaxf(acc[7] + bhi.w, 0.f);
        if (MODE == 1) {
            ((float4*)H)[(size_t)node * (G / 4) + lane * 2]     = olo;
            ((float4*)H)[(size_t)node * (G / 4) + lane * 2 + 1] = ohi;
        } else {
            int g = batch[node];
            red_add_v4(&g_pool[g * 32 + lane * 8], olo);
            red_add_v4(&g_pool[g * 32 + lane * 8 + 4], ohi);
        }
    }
}

// ---------------- FP16 hi/lo TC GEMM (m16n8k16, 3-term), register-prefetch ----------
// grid.y (seg) = 0,1,2: seg 0 writes fp32 Y0 (ld=BN); seg 1/2 write fp16 into Vh (ld=2*BN).
// Smem: A row-major [m][k] halfs; B stored transposed [n][k] halfs (k contiguous) so
// the m16n8k16 B fragment (k-adjacent half pair) is a single 4B load.
// Row stride 24 halfs (48B) makes fragment loads bank-conflict-free.
template <int BN>
__launch_bounds__(256, 2)
__global__ void gemm_tc_kernel(const float* __restrict__ A,
                               const float* __restrict__ B,
                               int M, int F, int ldn) {
    const int BM = 128, BK = 16;
    const int LDS = BK + 8;          // 24 halfs per row
    const int WARPS_N = BN / 32;
    const int WARPS_M = 8 / WARPS_N;
    const int WM = BM / WARPS_M;
    const int TM = WM / 16;
    const int TN = 4;
    const int BVEC = BK * BN / 4;
    const int BLOADS = (BVEC + 255) / 256;

    __shared__ __half As_hi[BM][LDS];
    __shared__ __half As_lo[BM][LDS];
    __shared__ __half Bst_hi[BN][LDS];
    __shared__ __half Bst_lo[BN][LDS];

    int t = threadIdx.x;
    int warp = t >> 5, lane = t & 31;
    int group = lane >> 2, tg = lane & 3;
    int warp_m = warp % WARPS_M;
    int warp_n = warp / WARPS_M;
    int m_w = warp_m * WM;
    int n_w = warp_n * 32;
    int m0 = blockIdx.x * BM;
    int seg = blockIdx.y;
    int n0 = seg * BN;

    float acc[TM][TN][4];
#pragma unroll
    for (int i = 0; i < TM; ++i)
#pragma unroll
        for (int j = 0; j < TN; ++j)
#pragma unroll
            for (int r = 0; r < 4; ++r) acc[i][j][r] = 0.f;

    float4 a_pref[2];
    float4 b_pref[BLOADS];

    // ---- prologue prefetch (k0 = 0)
#pragma unroll
    for (int l = 0; l < 2; ++l) {
        int idx = t + l * 256;
        int row = idx >> 2;
        int c4 = (idx & 3) * 4;
        int m = m0 + row;
        a_pref[l] = (m < M) ? *(const float4*)(A + (size_t)m * F + c4)
                            : make_float4(0.f, 0.f, 0.f, 0.f);
    }
#pragma unroll
    for (int l = 0; l < BLOADS; ++l) {
        int idx = t + l * 256;
        if (idx < BVEC) {
            int row = idx / (BN / 4);
            int c4 = (idx % (BN / 4)) * 4;
            b_pref[l] = *(const float4*)(B + (size_t)row * ldn + n0 + c4);
        }
    }

    for (int k0 = 0; k0 < F; k0 += BK) {
        // ---- store prefetched A tile with fp16 hi/lo split (row-major, k contiguous)
#pragma unroll
        for (int l = 0; l < 2; ++l) {
            int idx = t + l * 256;
            int row = idx >> 2;
            int c4 = (idx & 3) * 4;
            float4 v = a_pref[l];
            __half h[4], lo[4];
            split_h(v.x, h[0], lo[0]);
            split_h(v.y, h[1], lo[1]);
            split_h(v.z, h[2], lo[2]);
            split_h(v.w, h[3], lo[3]);
            *(__half2*)&As_hi[row][c4]     = __halves2half2(h[0], h[1]);
            *(__half2*)&As_hi[row][c4 + 2] = __halves2half2(h[2], h[3]);
            *(__half2*)&As_lo[row][c4]     = __halves2half2(lo[0], lo[1]);
            *(__half2*)&As_lo[row][c4 + 2] = __halves2half2(lo[2], lo[3]);
        }
        // ---- store prefetched B tile TRANSPOSED with hi/lo split
#pragma unroll
        for (int l = 0; l < BLOADS; ++l) {
            int idx = t + l * 256;
            if (idx < BVEC) {
                int krow = idx / (BN / 4);
                int c4 = (idx % (BN / 4)) * 4;
                float4 v = b_pref[l];
                __half h, lo;
                split_h(v.x, h, lo); Bst_hi[c4 + 0][krow] = h; Bst_lo[c4 + 0][krow] = lo;
                split_h(v.y, h, lo); Bst_hi[c4 + 1][krow] = h; Bst_lo[c4 + 1][krow] = lo;
                split_h(v.z, h, lo); Bst_hi[c4 + 2][krow] = h; Bst_lo[c4 + 2][krow] = lo;
                split_h(v.w, h, lo); Bst_hi[c4 + 3][krow] = h; Bst_lo[c4 + 3][krow] = lo;
            }
        }
        __syncthreads();

        // ---- prefetch next tile (overlaps with MMA below)
        int kn = k0 + BK;
        if (kn < F) {
#pragma unroll
            for (int l = 0; l < 2; ++l) {
                int idx = t + l * 256;
                int row = idx >> 2;
                int c4 = (idx & 3) * 4;
                int m = m0 + row;
                a_pref[l] = (m < M) ? *(const float4*)(A + (size_t)m * F + kn + c4)
                                    : make_float4(0.f, 0.f, 0.f, 0.f);
            }
#pragma unroll
            for (int l = 0; l < BLOADS; ++l) {
                int idx = t + l * 256;
                if (idx < BVEC) {
                    int row = idx / (BN / 4);
                    int c4 = (idx % (BN / 4)) * 4;
                    b_pref[l] = *(const float4*)(B + (size_t)(kn + row) * ldn + n0 + c4);
                }
            }
        }

        // ---- compute: one m16n8k16 step covers the whole BK=16 tile
        {
            uint32_t bh[TN][2], bl[TN][2];
#pragma unroll
            for (int j = 0; j < TN; ++j) {
                int n = n_w + j * 8 + group;
                bh[j][0] = *(const uint32_t*)&Bst_hi[n][2 * tg];
                bh[j][1] = *(const uint32_t*)&Bst_hi[n][2 * tg + 8];
                bl[j][0] = *(const uint32_t*)&Bst_lo[n][2 * tg];
                bl[j][1] = *(const uint32_t*)&Bst_lo[n][2 * tg + 8];
            }
#pragma unroll
            for (int i = 0; i < TM; ++i) {
                int mb = m_w + i * 16;
                uint32_t ah[4], al[4];
                ah[0] = *(const uint32_t*)&As_hi[mb + group][2 * tg];
                ah[1] = *(const uint32_t*)&As_hi[mb + group + 8][2 * tg];
                ah[2] = *(const uint32_t*)&As_hi[mb + group][2 * tg + 8];
                ah[3] = *(const uint32_t*)&As_hi[mb + group + 8][2 * tg + 8];
                al[0] = *(const uint32_t*)&As_lo[mb + group][2 * tg];
                al[1] = *(const uint32_t*)&As_lo[mb + group + 8][2 * tg];
                al[2] = *(const uint32_t*)&As_lo[mb + group][2 * tg + 8];
                al[3] = *(const uint32_t*)&As_lo[mb + group + 8][2 * tg + 8];
#pragma unroll
                for (int j = 0; j < TN; ++j) {
                    mma_f16(acc[i][j], ah, bh[j]);   // hi*hi
                    mma_f16(acc[i][j], ah, bl[j]);   // hi*lo
                    mma_f16(acc[i][j], al, bh[j]);   // lo*hi
                }
            }
        }
        __syncthreads();
    }

    // ---- epilogue: seg 0 -> fp32 Y0 (ld=BN); seg 1/2 -> fp16 Vh (ld=2*BN)
#pragma unroll
    for (int i = 0; i < TM; ++i) {
        int mb = m0 + m_w + i * 16;
        int row0 = mb + group;
        int row1 = mb + group + 8;
#pragma unroll
        for (int j = 0; j < TN; ++j) {
            int n = n_w + j * 8 + 2 * tg;
            if (seg == 0) {
                if (row0 < M) {
                    g_Y0[(size_t)row0 * BN + n]     = acc[i][j][0];
                    g_Y0[(size_t)row0 * BN + n + 1] = acc[i][j][1];
                }
                if (row1 < M) {
                    g_Y0[(size_t)row1 * BN + n]     = acc[i][j][2];
                    g_Y0[(size_t)row1 * BN + n + 1] = acc[i][j][3];
                }
            } else {
                int col = (seg - 1) * BN + n;
                if (row0 < M) {
                    __half2 h = __floats2half2_rn(acc[i][j][0], acc[i][j][1]);
                    *(__half2*)&g_Vh[(size_t)row0 * 2 * BN + col] = h;
                }
                if (row1 < M) {
                    __half2 h = __floats2half2_rn(acc[i][j][2], acc[i][j][3]);
                    *(__half2*)&g_Vh[(size_t)row1 * 2 * BN + col] = h;
                }
            }
        }
    }
}

// ---------------- final linear ----------------
__global__ void final_kernel(const float* __restrict__ Wl, const float* __restrict__ bl,
                             float* __restrict__ out) {
    int t = threadIdx.x;
    if (t >= NG * 2) return;
    int g = t >> 1;
    int j = t & 1;
    float cnt = fmaxf(g_cnt[g], 1.0f);
    float s = 0.f;
#pragma unroll
    for (int c = 0; c < 32; ++c) s += g_pool[g * 32 + c] * Wl[c * 2 + j];
    out[t] = s / cnt + bl[j];
}

// ---------------- host orchestration (single stream) ----------------
extern "C" void kernel_launch(void* const* d_in, const int* in_sizes, int n_in,
                              void* d_out, int out_size) {
    const float* x     = (const float*)d_in[0];
    const int*   ei    = (const int*)d_in[1];
    const float* ea    = (const float*)d_in[2];
    const int*   batch = (const int*)d_in[3];
    const float* W1    = (const float*)d_in[4];
    const float* b1    = (const float*)d_in[5];
    const float* W2    = (const float*)d_in[6];
    const float* b2    = (const float*)d_in[7];
    const float* W3    = (const float*)d_in[8];
    const float* b3    = (const float*)d_in[9];
    const float* Wl    = (const float*)d_in[10];
    const float* bl    = (const float*)d_in[11];
    const int* src = ei;
    const int* dst = ei + EE;

    float *pH1, *pH2, *pWc1, *pWc2, *pWc3;
    cudaGetSymbolAddress((void**)&pH1,  g_H1);
    cudaGetSymbolAddress((void**)&pH2,  g_H2);
    cudaGetSymbolAddress((void**)&pWc1, g_Wc1);
    cudaGetSymbolAddress((void**)&pWc2, g_Wc2);
    cudaGetSymbolAddress((void**)&pWc3, g_Wc3);

    const int T = 256;

    // preamble
    zero_all_kernel<<<CDIV(NN, T), T>>>();
    deg_count_kernel<<<CDIV(EE / 4, T), T>>>(src, dst, ea, batch);
    scan_phase1_kernel<<<SCAN_NBLK, 256>>>();
    scan_phase23_kernel<<<SCAN_NBLK, 256>>>();
    scatter_w_kernel<<<CDIV(EE / 4, T), T>>>(src, dst, ea);
    wprep_all_kernel<<<CDIV(160 * 128 + 128 * 64 + 64 * 32, T), T>>>(W1, W2, W3);

    // ---- layer 1: 160 -> 128 ----
    {
        dim3 grid(CDIV(NN, 128), 3);
        gemm_tc_kernel<128><<<grid, 256>>>(x, pWc1, NN, 160, 384);
    }
    gather_kernel<128, 0><<<CDIV(NN * 16, T), T>>>(nullptr, nullptr, nullptr);
    gather_kernel<128, 1><<<CDIV(NN * 16, T), T>>>(pH1, b1, nullptr);
    // ---- layer 2: 128 -> 64 ----
    {
        dim3 grid(CDIV(NN, 128), 3);
        gemm_tc_kernel<64><<<grid, 256>>>(pH1, pWc2, NN, 128, 192);
    }
    gather_kernel<64, 0><<<CDIV(NN * 8, T), T>>>(nullptr, nullptr, nullptr);
    gather_kernel<64, 1><<<CDIV(NN * 8, T), T>>>(pH2, b2, nullptr);
    // ---- layer 3: 64 -> 32 (pool fused into second gather) ----
    {
        dim3 grid(CDIV(NN, 128), 3);
        gemm_tc_kernel<32><<<grid, 256>>>(pH2, pWc3, NN, 64, 96);
    }
    gather_kernel<32, 0><<<CDIV(NN * 4, T), T>>>(nullptr, nullptr, nullptr);
    gather_kernel<32, 2><<<CDIV(NN * 4, T), T>>>(nullptr, b3, batch);

    final_kernel<<<1, 256>>>(Wl, bl, (float*)d_out);
}

// round 14
// speedup vs baseline: 1.0343x; 1.0343x over previous
#include <cuda_runtime.h>
#include <cuda_fp16.h>
#include <cstdint>

#define NN 50000
#define EE 500000
#define NG  128

#define CDIV(a,b) (((a)+(b)-1)/(b))
#define SCAN_NBLK CDIV(NN, 256)      // 196

// ---------------- device scratch (no allocation allowed) ----------------
__device__ __align__(16) float  g_dinv[NN];
__device__ __align__(16) __half g_Y0h[NN * 128];    // fp16 Y0 region (max G=128)
__device__ __align__(16) __half g_Vh[NN * 256];     // [V | V2] fp16, ld = 2*G (max 256)
__device__ __align__(16) float  g_H1[NN * 128];
__device__ __align__(16) float  g_H2[NN * 64];
__device__ __align__(16) float  g_Wc1[160 * 384];
__device__ __align__(16) float  g_Wc2[128 * 192];
__device__ __align__(16) float  g_Wc3[64 * 96];
__device__ __align__(16) float  g_pool[NG * 32];
__device__ __align__(16) float  g_cnt[NG];
__device__ int   g_done;
// CSR (indexed by dst): packed (src, w-bits)
__device__ int   g_rowptr[NN + 1];
__device__ int   g_fill[NN];
__device__ int   g_bsum[SCAN_NBLK];
__device__ __align__(16) int2  g_csr[EE];

// ---------------- helpers ----------------
__device__ __forceinline__ void red_add_v4(float* addr, float4 v) {
    asm volatile("red.global.add.v4.f32 [%0], {%1,%2,%3,%4};"
                 :: "l"(addr), "f"(v.x), "f"(v.y), "f"(v.z), "f"(v.w)
                 : "memory");
}

__device__ __forceinline__ float tf32_hi(float x) {
    uint32_t u;
    asm("cvt.rna.tf32.f32 %0, %1;" : "=r"(u) : "f"(x));
    return __uint_as_float(u);
}

__device__ __forceinline__ void mma_tf32(float* c, const uint32_t* a, const uint32_t* b) {
    asm volatile("mma.sync.aligned.m16n8k8.row.col.f32.tf32.tf32.f32 "
                 "{%0,%1,%2,%3}, {%4,%5,%6,%7}, {%8,%9}, {%0,%1,%2,%3};"
                 : "+f"(c[0]), "+f"(c[1]), "+f"(c[2]), "+f"(c[3])
                 : "r"(a[0]), "r"(a[1]), "r"(a[2]), "r"(a[3]),
                   "r"(b[0]), "r"(b[1]));
}

// 8 halfs (uint4) -> 8 floats
__device__ __forceinline__ void h8_to_f8(uint4 u, float* f) {
    __half2 a = *(__half2*)&u.x;
    __half2 b = *(__half2*)&u.y;
    __half2 c = *(__half2*)&u.z;
    __half2 d = *(__half2*)&u.w;
    float2 fa = __half22float2(a), fb = __half22float2(b);
    float2 fc = __half22float2(c), fd = __half22float2(d);
    f[0] = fa.x; f[1] = fa.y; f[2] = fb.x; f[3] = fb.y;
    f[4] = fc.x; f[5] = fc.y; f[6] = fd.x; f[7] = fd.y;
}

__device__ __forceinline__ uint4 f8_to_h8(const float* f) {
    __half2 a = __floats2half2_rn(f[0], f[1]);
    __half2 b = __floats2half2_rn(f[2], f[3]);
    __half2 c = __floats2half2_rn(f[4], f[5]);
    __half2 d = __floats2half2_rn(f[6], f[7]);
    uint4 u;
    u.x = *(uint32_t*)&a; u.y = *(uint32_t*)&b;
    u.z = *(uint32_t*)&c; u.w = *(uint32_t*)&d;
    return u;
}

// ---------------- weight prep helper: Wc[f] = [W0-W2 | W1 | 2*W2] ----------------
__device__ __forceinline__ void wprep_one(const float* __restrict__ W, float* __restrict__ Wc,
                                          int F, int G, int t) {
    int f = t / G;
    int c = t - f * G;
    float w0 = W[t];
    float w1 = W[F * G + t];
    float w2 = W[2 * F * G + t];
    Wc[f * 3 * G + c]         = w0 - w2;
    Wc[f * 3 * G + G + c]     = w1;
    Wc[f * 3 * G + 2 * G + c] = 2.f * w2;
}

// ---------------- fused preamble: zero + weight prep ----------------
__global__ void zero_wprep_kernel(const float* __restrict__ W1, const float* __restrict__ W2,
                                  const float* __restrict__ W3) {
    int i = blockIdx.x * blockDim.x + threadIdx.x;
    if (i < NN) { g_dinv[i] = 0.f; g_fill[i] = 0; }
    if (i < NG * 32) g_pool[i] = 0.f;
    if (i < NG) g_cnt[i] = 0.f;
    if (i == 0) g_done = 0;
    const int S1 = 160 * 128, S2 = S1 + 128 * 64, S3 = S2 + 64 * 32;
    if (i < S1)      wprep_one(W1, g_Wc1, 160, 128, i);
    else if (i < S2) wprep_one(W2, g_Wc2, 128, 64, i - S1);
    else if (i < S3) wprep_one(W3, g_Wc3, 64, 32, i - S2);
}

// 4 edges / thread: degree accumulation + CSR row counting + per-graph node counts
__global__ void deg_count_kernel(const int* __restrict__ src, const int* __restrict__ dst,
                                 const float* __restrict__ ea, const int* __restrict__ batch) {
    int t = blockIdx.x * blockDim.x + threadIdx.x;
    if (t < EE / 4) {
        int4  s4 = ((const int4*)src)[t];
        int4  d4 = ((const int4*)dst)[t];
        float4 a4 = ((const float4*)ea)[t];
        atomicAdd(&g_dinv[s4.x], a4.x);
        atomicAdd(&g_dinv[s4.y], a4.y);
        atomicAdd(&g_dinv[s4.z], a4.z);
        atomicAdd(&g_dinv[s4.w], a4.w);
        atomicAdd(&g_fill[d4.x], 1);
        atomicAdd(&g_fill[d4.y], 1);
        atomicAdd(&g_fill[d4.z], 1);
        atomicAdd(&g_fill[d4.w], 1);
    }
    if (t < NN / 4) {
        int4 b4 = ((const int4*)batch)[t];
        atomicAdd(&g_cnt[b4.x], 1.0f);
        atomicAdd(&g_cnt[b4.y], 1.0f);
        atomicAdd(&g_cnt[b4.z], 1.0f);
        atomicAdd(&g_cnt[b4.w], 1.0f);
    }
}

// ---------------- multi-block scan of g_fill -> g_rowptr ----------------
__global__ void scan_phase1_kernel() {
    __shared__ int sh[256];
    int tid = threadIdx.x;
    int i = blockIdx.x * 256 + tid;
    int c = (i < NN) ? g_fill[i] : 0;
    if (i < NN) {
        float d = g_dinv[i];
        g_dinv[i] = (d > 0.f) ? rsqrtf(d) : 0.f;
    }
    int v = c;
    sh[tid] = v;
    __syncthreads();
#pragma unroll
    for (int off = 1; off < 256; off <<= 1) {
        int t = (tid >= off) ? sh[tid - off] : 0;
        __syncthreads();
        v += t;
        sh[tid] = v;
        __syncthreads();
    }
    if (i < NN) g_rowptr[i] = v - c;
    if (tid == 255) g_bsum[blockIdx.x] = sh[255];
}

__global__ void scan_phase23_kernel() {
    __shared__ int sh[256];
    int tid = threadIdx.x;
    int c = (tid < SCAN_NBLK) ? g_bsum[tid] : 0;
    int v = c;
    sh[tid] = v;
    __syncthreads();
#pragma unroll
    for (int off = 1; off < 256; off <<= 1) {
        int t = (tid >= off) ? sh[tid - off] : 0;
        __syncthreads();
        v += t;
        sh[tid] = v;
        __syncthreads();
    }
    int boff = (blockIdx.x > 0) ? sh[blockIdx.x - 1] : 0;
    __syncthreads();
    int i = blockIdx.x * 256 + tid;
    if (i < NN) {
        int r = g_rowptr[i] + boff;
        g_rowptr[i] = r;
        g_fill[i] = r;
    }
    if (i == 0) g_rowptr[NN] = EE;
}

// 4 edges / thread: scatter into packed CSR with normalized weight computed inline
__global__ void scatter_w_kernel(const int* __restrict__ src, const int* __restrict__ dst,
                                 const float* __restrict__ ea) {
    int t = blockIdx.x * blockDim.x + threadIdx.x;
    if (t >= EE / 4) return;
    int4  s4 = ((const int4*)src)[t];
    int4  d4 = ((const int4*)dst)[t];
    float4 a4 = ((const float4*)ea)[t];

    float w0 = -g_dinv[s4.x] * a4.x * g_dinv[d4.x];
    float w1 = -g_dinv[s4.y] * a4.y * g_dinv[d4.y];
    float w2 = -g_dinv[s4.z] * a4.z * g_dinv[d4.z];
    float w3 = -g_dinv[s4.w] * a4.w * g_dinv[d4.w];

    int p0 = atomicAdd(&g_fill[d4.x], 1);
    int p1 = atomicAdd(&g_fill[d4.y], 1);
    int p2 = atomicAdd(&g_fill[d4.z], 1);
    int p3 = atomicAdd(&g_fill[d4.w], 1);

    g_csr[p0] = make_int2(s4.x, __float_as_int(w0));
    g_csr[p1] = make_int2(s4.y, __float_as_int(w1));
    g_csr[p2] = make_int2(s4.z, __float_as_int(w2));
    g_csr[p3] = make_int2(s4.w, __float_as_int(w3));
}

// ---------------- CSR gather propagate (fp16, 16B lanes, packed CSR) ----------------
// Vh per node: 2G halfs = G/4 uint4; V region uint4 [0, G/8), V2 region [G/8, G/4)
// MODE 0: Vh.V[n]  = Vh.V[n] + sum_e w * Vh.V2[src]       (Z = V + P V2)
// MODE 1: H[n]     = relu(Y0h[n] + sum_e w * Vh.V[src] + b)
// MODE 2: pool[batch[n]] += relu(...); last block computes final linear
template <int G, int MODE>
__global__ void gather_kernel(float* __restrict__ H,
                              const float* __restrict__ bias,
                              const int* __restrict__ batch,
                              const float* __restrict__ Wl,
                              const float* __restrict__ bl,
                              float* __restrict__ out) {
    const int LPN = G / 8;
    const int LDH = G / 4;
    int tid = blockIdx.x * blockDim.x + threadIdx.x;
    int node = tid / LPN;
    int lane = tid % LPN;

    if (node < NN) {
        uint4* vh4 = (uint4*)g_Vh;
        int beg = g_rowptr[node];
        int end = g_rowptr[node + 1];

        const int srcoff = (MODE == 0) ? LPN : 0;
        float acc[8];
        if (MODE == 0) {
            h8_to_f8(vh4[(size_t)node * LDH + lane], acc);
        } else {
            h8_to_f8(((const uint4*)g_Y0h)[(size_t)node * LPN + lane], acc);
        }

        int j = beg;
        for (; j + 3 < end; j += 4) {
            int2 e[4]; uint4 v[4];
#pragma unroll
            for (int u = 0; u < 4; ++u) e[u] = g_csr[j + u];
#pragma unroll
            for (int u = 0; u < 4; ++u) v[u] = vh4[(size_t)e[u].x * LDH + srcoff + lane];
#pragma unroll
            for (int u = 0; u < 4; ++u) {
                float w = __int_as_float(e[u].y);
                float f[8];
                h8_to_f8(v[u], f);
#pragma unroll
                for (int r = 0; r < 8; ++r) acc[r] = fmaf(w, f[r], acc[r]);
            }
        }
        for (; j < end; ++j) {
            int2 e = g_csr[j];
            float w = __int_as_float(e.y);
            float f[8];
            h8_to_f8(vh4[(size_t)e.x * LDH + srcoff + lane], f);
#pragma unroll
            for (int r = 0; r < 8; ++r) acc[r] = fmaf(w, f[r], acc[r]);
        }

        if (MODE == 0) {
            vh4[(size_t)node * LDH + lane] = f8_to_h8(acc);
        } else {
            float4 blo = ((const float4*)bias)[lane * 2];
            float4 bhi = ((const float4*)bias)[lane * 2 + 1];
            float4 olo, ohi;
            olo.x = fmaxf(acc[0] + blo.x, 0.f);
            olo.y = fmaxf(acc[1] + blo.y, 0.f);
            olo.z = fmaxf(acc[2] + blo.z, 0.f);
            olo.w = fmaxf(acc[3] + blo.w, 0.f);
            ohi.x = fmaxf(acc[4] + bhi.x, 0.f);
            ohi.y = fmaxf(acc[5] + bhi.y, 0.f);
            ohi.z = fmaxf(acc[6] + bhi.z, 0.f);
            ohi.w = fmaxf(acc[7] + bhi.w, 0.f);
            if (MODE == 1) {
                ((float4*)H)[(size_t)node * (G / 4) + lane * 2]     = olo;
                ((float4*)H)[(size_t)node * (G / 4) + lane * 2 + 1] = ohi;
            } else {
                int g = batch[node];
                red_add_v4(&g_pool[g * 32 + lane * 8], olo);
                red_add_v4(&g_pool[g * 32 + lane * 8 + 4], ohi);
            }
        }
    }

    if (MODE == 2) {
        // last-block pattern: the final block to arrive computes the output linear
        __threadfence();
        __shared__ int is_last;
        if (threadIdx.x == 0)
            is_last = (atomicAdd(&g_done, 1) == (int)gridDim.x - 1);
        __syncthreads();
        if (is_last) {
            __threadfence();
            int t = threadIdx.x;
            if (t < NG * 2) {
                int g = t >> 1;
                int jj = t & 1;
                float cnt = fmaxf(g_cnt[g], 1.0f);
                float s = 0.f;
#pragma unroll
                for (int c = 0; c < 32; ++c) s += g_pool[g * 32 + c] * Wl[c * 2 + jj];
                out[t] = s / cnt + bl[jj];
            }
        }
    }
}

// ---------------- TF32 TC GEMM, hi/lo 3-term, register-prefetch pipeline --------------
// grid.y (seg) = 0,1,2: seg 0 writes fp16 Y0h (ld=BN); seg 1/2 write fp16 Vh (ld=2*BN).
template <int BN>
__launch_bounds__(256, 2)
__global__ void gemm_tc_kernel(const float* __restrict__ A,
                               const float* __restrict__ B,
                               int M, int F, int ldn) {
    const int BM = 128, BK = 16;
    const int WARPS_N = BN / 32;
    const int WARPS_M = 8 / WARPS_N;
    const int WM = BM / WARPS_M;
    const int TM = WM / 16;
    const int TN = 4;
    const int BVEC = BK * BN / 4;
    const int BLOADS = (BVEC + 255) / 256;

    __shared__ float As_hi[BM][BK + 4];
    __shared__ float As_lo[BM][BK + 4];
    __shared__ float Bs_hi[BK][BN + 4];
    __shared__ float Bs_lo[BK][BN + 4];

    int t = threadIdx.x;
    int warp = t >> 5, lane = t & 31;
    int group = lane >> 2, tg = lane & 3;
    int warp_m = warp % WARPS_M;
    int warp_n = warp / WARPS_M;
    int m_w = warp_m * WM;
    int n_w = warp_n * 32;
    int m0 = blockIdx.x * BM;
    int seg = blockIdx.y;
    int n0 = seg * BN;

    float acc[TM][TN][4];
#pragma unroll
    for (int i = 0; i < TM; ++i)
#pragma unroll
        for (int j = 0; j < TN; ++j)
#pragma unroll
            for (int r = 0; r < 4; ++r) acc[i][j][r] = 0.f;

    float4 a_pref[2];
    float4 b_pref[BLOADS];

#pragma unroll
    for (int l = 0; l < 2; ++l) {
        int idx = t + l * 256;
        int row = idx >> 2;
        int c4 = (idx & 3) * 4;
        int m = m0 + row;
        a_pref[l] = (m < M) ? *(const float4*)(A + (size_t)m * F + c4)
                            : make_float4(0.f, 0.f, 0.f, 0.f);
    }
#pragma unroll
    for (int l = 0; l < BLOADS; ++l) {
        int idx = t + l * 256;
        if (idx < BVEC) {
            int row = idx / (BN / 4);
            int c4 = (idx % (BN / 4)) * 4;
            b_pref[l] = *(const float4*)(B + (size_t)row * ldn + n0 + c4);
        }
    }

    for (int k0 = 0; k0 < F; k0 += BK) {
#pragma unroll
        for (int l = 0; l < 2; ++l) {
            int idx = t + l * 256;
            int row = idx >> 2;
            int c4 = (idx & 3) * 4;
            float4 v = a_pref[l];
            float hx = tf32_hi(v.x), hy = tf32_hi(v.y), hz = tf32_hi(v.z), hw = tf32_hi(v.w);
            *(float4*)&As_hi[row][c4] = make_float4(hx, hy, hz, hw);
            *(float4*)&As_lo[row][c4] = make_float4(tf32_hi(v.x - hx), tf32_hi(v.y - hy),
                                                    tf32_hi(v.z - hz), tf32_hi(v.w - hw));
        }
#pragma unroll
        for (int l = 0; l < BLOADS; ++l) {
            int idx = t + l * 256;
            if (idx < BVEC) {
                int row = idx / (BN / 4);
                int c4 = (idx % (BN / 4)) * 4;
                float4 v = b_pref[l];
                float hx = tf32_hi(v.x), hy = tf32_hi(v.y), hz = tf32_hi(v.z), hw = tf32_hi(v.w);
                *(float4*)&Bs_hi[row][c4] = make_float4(hx, hy, hz, hw);
                *(float4*)&Bs_lo[row][c4] = make_float4(tf32_hi(v.x - hx), tf32_hi(v.y - hy),
                                                        tf32_hi(v.z - hz), tf32_hi(v.w - hw));
            }
        }
        __syncthreads();

        int kn = k0 + BK;
        if (kn < F) {
#pragma unroll
            for (int l = 0; l < 2; ++l) {
                int idx = t + l * 256;
                int row = idx >> 2;
                int c4 = (idx & 3) * 4;
                int m = m0 + row;
                a_pref[l] = (m < M) ? *(const float4*)(A + (size_t)m * F + kn + c4)
                                    : make_float4(0.f, 0.f, 0.f, 0.f);
            }
#pragma unroll
            for (int l = 0; l < BLOADS; ++l) {
                int idx = t + l * 256;
                if (idx < BVEC) {
                    int row = idx / (BN / 4);
                    int c4 = (idx % (BN / 4)) * 4;
                    b_pref[l] = *(const float4*)(B + (size_t)(kn + row) * ldn + n0 + c4);
                }
            }
        }

#pragma unroll
        for (int ks = 0; ks < 2; ++ks) {
            int kb = ks * 8;
            uint32_t bh[TN][2], bl[TN][2];
#pragma unroll
            for (int j = 0; j < TN; ++j) {
                int n = n_w + j * 8 + group;
                bh[j][0] = __float_as_uint(Bs_hi[kb + tg][n]);
                bh[j][1] = __float_as_uint(Bs_hi[kb + tg + 4][n]);
                bl[j][0] = __float_as_uint(Bs_lo[kb + tg][n]);
                bl[j][1] = __float_as_uint(Bs_lo[kb + tg + 4][n]);
            }
#pragma unroll
            for (int i = 0; i < TM; ++i) {
                int mb = m_w + i * 16;
                uint32_t ah[4], al[4];
                ah[0] = __float_as_uint(As_hi[mb + group][kb + tg]);
                ah[1] = __float_as_uint(As_hi[mb + group + 8][kb + tg]);
                ah[2] = __float_as_uint(As_hi[mb + group][kb + tg + 4]);
                ah[3] = __float_as_uint(As_hi[mb + group + 8][kb + tg + 4]);
                al[0] = __float_as_uint(As_lo[mb + group][kb + tg]);
                al[1] = __float_as_uint(As_lo[mb + group + 8][kb + tg]);
                al[2] = __float_as_uint(As_lo[mb + group][kb + tg + 4]);
                al[3] = __float_as_uint(As_lo[mb + group + 8][kb + tg + 4]);
#pragma unroll
                for (int j = 0; j < TN; ++j) {
                    mma_tf32(acc[i][j], ah, bh[j]);
                    mma_tf32(acc[i][j], ah, bl[j]);
                    mma_tf32(acc[i][j], al, bh[j]);
                }
            }
        }
        __syncthreads();
    }

    // ---- epilogue: all segs write fp16; seg 0 -> Y0h (ld=BN), seg 1/2 -> Vh (ld=2*BN)
#pragma unroll
    for (int i = 0; i < TM; ++i) {
        int mb = m0 + m_w + i * 16;
        int row0 = mb + group;
        int row1 = mb + group + 8;
#pragma unroll
        for (int j = 0; j < TN; ++j) {
            int n = n_w + j * 8 + 2 * tg;
            if (seg == 0) {
                if (row0 < M) {
                    __half2 h = __floats2half2_rn(acc[i][j][0], acc[i][j][1]);
                    *(__half2*)&g_Y0h[(size_t)row0 * BN + n] = h;
                }
                if (row1 < M) {
                    __half2 h = __floats2half2_rn(acc[i][j][2], acc[i][j][3]);
                    *(__half2*)&g_Y0h[(size_t)row1 * BN + n] = h;
                }
            } else {
                int col = (seg - 1) * BN + n;
                if (row0 < M) {
                    __half2 h = __floats2half2_rn(acc[i][j][0], acc[i][j][1]);
                    *(__half2*)&g_Vh[(size_t)row0 * 2 * BN + col] = h;
                }
                if (row1 < M) {
                    __half2 h = __floats2half2_rn(acc[i][j][2], acc[i][j][3]);
                    *(__half2*)&g_Vh[(size_t)row1 * 2 * BN + col] = h;
                }
            }
        }
    }
}

// ---------------- host orchestration (single stream) ----------------
extern "C" void kernel_launch(void* const* d_in, const int* in_sizes, int n_in,
                              void* d_out, int out_size) {
    const float* x     = (const float*)d_in[0];
    const int*   ei    = (const int*)d_in[1];
    const float* ea    = (const float*)d_in[2];
    const int*   batch = (const int*)d_in[3];
    const float* W1    = (const float*)d_in[4];
    const float* b1    = (const float*)d_in[5];
    const float* W2    = (const float*)d_in[6];
    const float* b2    = (const float*)d_in[7];
    const float* W3    = (const float*)d_in[8];
    const float* b3    = (const float*)d_in[9];
    const float* Wl    = (const float*)d_in[10];
    const float* bl    = (const float*)d_in[11];
    const int* src = ei;
    const int* dst = ei + EE;

    float *pH1, *pH2, *pWc1, *pWc2, *pWc3;
    cudaGetSymbolAddress((void**)&pH1,  g_H1);
    cudaGetSymbolAddress((void**)&pH2,  g_H2);
    cudaGetSymbolAddress((void**)&pWc1, g_Wc1);
    cudaGetSymbolAddress((void**)&pWc2, g_Wc2);
    cudaGetSymbolAddress((void**)&pWc3, g_Wc3);

    const int T = 256;
    float* outp = (float*)d_out;

    // preamble
    zero_wprep_kernel<<<CDIV(NN, T), T>>>(W1, W2, W3);
    deg_count_kernel<<<CDIV(EE / 4, T), T>>>(src, dst, ea, batch);
    scan_phase1_kernel<<<SCAN_NBLK, 256>>>();
    scan_phase23_kernel<<<SCAN_NBLK, 256>>>();
    scatter_w_kernel<<<CDIV(EE / 4, T), T>>>(src, dst, ea);

    // ---- layer 1: 160 -> 128 ----
    {
        dim3 grid(CDIV(NN, 128), 3);
        gemm_tc_kernel<128><<<grid, 256>>>(x, pWc1, NN, 160, 384);
    }
    gather_kernel<128, 0><<<CDIV(NN * 16, T), T>>>(nullptr, nullptr, nullptr, nullptr, nullptr, nullptr);
    gather_kernel<128, 1><<<CDIV(NN * 16, T), T>>>(pH1, b1, nullptr, nullptr, nullptr, nullptr);
    // ---- layer 2: 128 -> 64 ----
    {
        dim3 grid(CDIV(NN, 128), 3);
        gemm_tc_kernel<64><<<grid, 256>>>(pH1, pWc2, NN, 128, 192);
    }
    gather_kernel<64, 0><<<CDIV(NN * 8, T), T>>>(nullptr, nullptr, nullptr, nullptr, nullptr, nullptr);
    gather_kernel<64, 1><<<CDIV(NN * 8, T), T>>>(pH2, b2, nullptr, nullptr, nullptr, nullptr);
    // ---- layer 3: 64 -> 32 (pool + final linear fused) ----
    {
        dim3 grid(CDIV(NN, 128), 3);
        gemm_tc_kernel<32><<<grid, 256>>>(pH2, pWc3, NN, 64, 96);
    }
    gather_kernel<32, 0><<<CDIV(NN * 4, T), T>>>(nullptr, nullptr, nullptr, nullptr, nullptr, nullptr);
    gather_kernel<32, 2><<<CDIV(NN * 4, T), T>>>(nullptr, b3, batch, Wl, bl, outp);
}

// round 15
// speedup vs baseline: 1.0935x; 1.0572x over previous
#include <cuda_runtime.h>
#include <cuda_fp16.h>
#include <cstdint>

#define NN 50000
#define EE 500000
#define NG  128

#define CDIV(a,b) (((a)+(b)-1)/(b))
#define SCAN_NBLK CDIV(NN, 256)      // 196

// ---------------- device scratch (no allocation allowed) ----------------
__device__ __align__(16) float  g_dinv[NN];
__device__ __align__(16) __half g_Y0h[NN * 128];    // fp16 Y0 region (max G=128)
__device__ __align__(16) __half g_Vh[NN * 256];     // [V | V2] fp16, ld = 2*G (max 256)
__device__ __align__(16) __half g_H1h[NN * 128];
__device__ __align__(16) __half g_H2h[NN * 64];
__device__ __align__(16) float  g_Wc1[160 * 384];
__device__ __align__(16) float  g_Wc2[128 * 192];
__device__ __align__(16) float  g_Wc3[64 * 96];
__device__ __align__(16) float  g_pool[NG * 32];
__device__ __align__(16) float  g_cnt[NG];
__device__ int   g_done;
// CSR (indexed by dst): packed (src, w-bits)
__device__ int   g_rowptr[NN + 1];
__device__ int   g_fill[NN];
__device__ int   g_bsum[SCAN_NBLK];
__device__ __align__(16) int2  g_csr[EE];

// ---------------- helpers ----------------
__device__ __forceinline__ void red_add_v4(float* addr, float4 v) {
    asm volatile("red.global.add.v4.f32 [%0], {%1,%2,%3,%4};"
                 :: "l"(addr), "f"(v.x), "f"(v.y), "f"(v.z), "f"(v.w)
                 : "memory");
}

__device__ __forceinline__ float tf32_hi(float x) {
    uint32_t u;
    asm("cvt.rna.tf32.f32 %0, %1;" : "=r"(u) : "f"(x));
    return __uint_as_float(u);
}

__device__ __forceinline__ void mma_tf32(float* c, const uint32_t* a, const uint32_t* b) {
    asm volatile("mma.sync.aligned.m16n8k8.row.col.f32.tf32.tf32.f32 "
                 "{%0,%1,%2,%3}, {%4,%5,%6,%7}, {%8,%9}, {%0,%1,%2,%3};"
                 : "+f"(c[0]), "+f"(c[1]), "+f"(c[2]), "+f"(c[3])
                 : "r"(a[0]), "r"(a[1]), "r"(a[2]), "r"(a[3]),
                   "r"(b[0]), "r"(b[1]));
}

// 8 halfs (uint4) -> 8 floats
__device__ __forceinline__ void h8_to_f8(uint4 u, float* f) {
    __half2 a = *(__half2*)&u.x;
    __half2 b = *(__half2*)&u.y;
    __half2 c = *(__half2*)&u.z;
    __half2 d = *(__half2*)&u.w;
    float2 fa = __half22float2(a), fb = __half22float2(b);
    float2 fc = __half22float2(c), fd = __half22float2(d);
    f[0] = fa.x; f[1] = fa.y; f[2] = fb.x; f[3] = fb.y;
    f[4] = fc.x; f[5] = fc.y; f[6] = fd.x; f[7] = fd.y;
}

__device__ __forceinline__ uint4 f8_to_h8(const float* f) {
    __half2 a = __floats2half2_rn(f[0], f[1]);
    __half2 b = __floats2half2_rn(f[2], f[3]);
    __half2 c = __floats2half2_rn(f[4], f[5]);
    __half2 d = __floats2half2_rn(f[6], f[7]);
    uint4 u;
    u.x = *(uint32_t*)&a; u.y = *(uint32_t*)&b;
    u.z = *(uint32_t*)&c; u.w = *(uint32_t*)&d;
    return u;
}

// ---------------- weight prep helper: Wc[f] = [W0-W2 | W1 | 2*W2] ----------------
__device__ __forceinline__ void wprep_one(const float* __restrict__ W, float* __restrict__ Wc,
                                          int F, int G, int t) {
    int f = t / G;
    int c = t - f * G;
    float w0 = W[t];
    float w1 = W[F * G + t];
    float w2 = W[2 * F * G + t];
    Wc[f * 3 * G + c]         = w0 - w2;
    Wc[f * 3 * G + G + c]     = w1;
    Wc[f * 3 * G + 2 * G + c] = 2.f * w2;
}

// ---------------- fused preamble: zero + weight prep ----------------
__global__ void zero_wprep_kernel(const float* __restrict__ W1, const float* __restrict__ W2,
                                  const float* __restrict__ W3) {
    int i = blockIdx.x * blockDim.x + threadIdx.x;
    if (i < NN) { g_dinv[i] = 0.f; g_fill[i] = 0; }
    if (i < NG * 32) g_pool[i] = 0.f;
    if (i < NG) g_cnt[i] = 0.f;
    if (i == 0) g_done = 0;
    const int S1 = 160 * 128, S2 = S1 + 128 * 64, S3 = S2 + 64 * 32;
    if (i < S1)      wprep_one(W1, g_Wc1, 160, 128, i);
    else if (i < S2) wprep_one(W2, g_Wc2, 128, 64, i - S1);
    else if (i < S3) wprep_one(W3, g_Wc3, 64, 32, i - S2);
}

// 4 edges / thread: degree accumulation + CSR row counting + per-graph node counts
__global__ void deg_count_kernel(const int* __restrict__ src, const int* __restrict__ dst,
                                 const float* __restrict__ ea, const int* __restrict__ batch) {
    int t = blockIdx.x * blockDim.x + threadIdx.x;
    if (t < EE / 4) {
        int4  s4 = ((const int4*)src)[t];
        int4  d4 = ((const int4*)dst)[t];
        float4 a4 = ((const float4*)ea)[t];
        atomicAdd(&g_dinv[s4.x], a4.x);
        atomicAdd(&g_dinv[s4.y], a4.y);
        atomicAdd(&g_dinv[s4.z], a4.z);
        atomicAdd(&g_dinv[s4.w], a4.w);
        atomicAdd(&g_fill[d4.x], 1);
        atomicAdd(&g_fill[d4.y], 1);
        atomicAdd(&g_fill[d4.z], 1);
        atomicAdd(&g_fill[d4.w], 1);
    }
    if (t < NN / 4) {
        int4 b4 = ((const int4*)batch)[t];
        atomicAdd(&g_cnt[b4.x], 1.0f);
        atomicAdd(&g_cnt[b4.y], 1.0f);
        atomicAdd(&g_cnt[b4.z], 1.0f);
        atomicAdd(&g_cnt[b4.w], 1.0f);
    }
}

// ---------------- multi-block scan of g_fill -> g_rowptr ----------------
__global__ void scan_phase1_kernel() {
    __shared__ int sh[256];
    int tid = threadIdx.x;
    int i = blockIdx.x * 256 + tid;
    int c = (i < NN) ? g_fill[i] : 0;
    if (i < NN) {
        float d = g_dinv[i];
        g_dinv[i] = (d > 0.f) ? rsqrtf(d) : 0.f;
    }
    int v = c;
    sh[tid] = v;
    __syncthreads();
#pragma unroll
    for (int off = 1; off < 256; off <<= 1) {
        int t = (tid >= off) ? sh[tid - off] : 0;
        __syncthreads();
        v += t;
        sh[tid] = v;
        __syncthreads();
    }
    if (i < NN) g_rowptr[i] = v - c;
    if (tid == 255) g_bsum[blockIdx.x] = sh[255];
}

__global__ void scan_phase23_kernel() {
    __shared__ int sh[256];
    int tid = threadIdx.x;
    int c = (tid < SCAN_NBLK) ? g_bsum[tid] : 0;
    int v = c;
    sh[tid] = v;
    __syncthreads();
#pragma unroll
    for (int off = 1; off < 256; off <<= 1) {
        int t = (tid >= off) ? sh[tid - off] : 0;
        __syncthreads();
        v += t;
        sh[tid] = v;
        __syncthreads();
    }
    int boff = (blockIdx.x > 0) ? sh[blockIdx.x - 1] : 0;
    __syncthreads();
    int i = blockIdx.x * 256 + tid;
    if (i < NN) {
        int r = g_rowptr[i] + boff;
        g_rowptr[i] = r;
        g_fill[i] = r;
    }
    if (i == 0) g_rowptr[NN] = EE;
}

// 4 edges / thread: scatter into packed CSR with normalized weight computed inline
__global__ void scatter_w_kernel(const int* __restrict__ src, const int* __restrict__ dst,
                                 const float* __restrict__ ea) {
    int t = blockIdx.x * blockDim.x + threadIdx.x;
    if (t >= EE / 4) return;
    int4  s4 = ((const int4*)src)[t];
    int4  d4 = ((const int4*)dst)[t];
    float4 a4 = ((const float4*)ea)[t];

    float w0 = -g_dinv[s4.x] * a4.x * g_dinv[d4.x];
    float w1 = -g_dinv[s4.y] * a4.y * g_dinv[d4.y];
    float w2 = -g_dinv[s4.z] * a4.z * g_dinv[d4.z];
    float w3 = -g_dinv[s4.w] * a4.w * g_dinv[d4.w];

    int p0 = atomicAdd(&g_fill[d4.x], 1);
    int p1 = atomicAdd(&g_fill[d4.y], 1);
    int p2 = atomicAdd(&g_fill[d4.z], 1);
    int p3 = atomicAdd(&g_fill[d4.w], 1);

    g_csr[p0] = make_int2(s4.x, __float_as_int(w0));
    g_csr[p1] = make_int2(s4.y, __float_as_int(w1));
    g_csr[p2] = make_int2(s4.z, __float_as_int(w2));
    g_csr[p3] = make_int2(s4.w, __float_as_int(w3));
}

// ---------------- CSR gather propagate (fp16, 16B lanes, packed CSR) ----------------
// Vh per node: 2G halfs = G/4 uint4; V region uint4 [0, G/8), V2 region [G/8, G/4)
// MODE 0: Vh.V[n]  = Vh.V[n] + sum_e w * Vh.V2[src]       (Z = V + P V2)
// MODE 1: Hh[n]    = relu(Y0h[n] + sum_e w * Vh.V[src] + b)   (fp16 output)
// MODE 2: pool[batch[n]] += relu(...); last block computes final linear
template <int G, int MODE>
__global__ void gather_kernel(__half* __restrict__ H,
                              const float* __restrict__ bias,
                              const int* __restrict__ batch,
                              const float* __restrict__ Wl,
                              const float* __restrict__ bl,
                              float* __restrict__ out) {
    const int LPN = G / 8;
    const int LDH = G / 4;
    int tid = blockIdx.x * blockDim.x + threadIdx.x;
    int node = tid / LPN;
    int lane = tid % LPN;

    if (node < NN) {
        uint4* vh4 = (uint4*)g_Vh;
        int beg = g_rowptr[node];
        int end = g_rowptr[node + 1];

        const int srcoff = (MODE == 0) ? LPN : 0;
        float acc[8];
        if (MODE == 0) {
            h8_to_f8(vh4[(size_t)node * LDH + lane], acc);
        } else {
            h8_to_f8(((const uint4*)g_Y0h)[(size_t)node * LPN + lane], acc);
        }

        int j = beg;
        for (; j + 3 < end; j += 4) {
            int2 e[4]; uint4 v[4];
#pragma unroll
            for (int u = 0; u < 4; ++u) e[u] = g_csr[j + u];
#pragma unroll
            for (int u = 0; u < 4; ++u) v[u] = vh4[(size_t)e[u].x * LDH + srcoff + lane];
#pragma unroll
            for (int u = 0; u < 4; ++u) {
                float w = __int_as_float(e[u].y);
                float f[8];
                h8_to_f8(v[u], f);
#pragma unroll
                for (int r = 0; r < 8; ++r) acc[r] = fmaf(w, f[r], acc[r]);
            }
        }
        for (; j < end; ++j) {
            int2 e = g_csr[j];
            float w = __int_as_float(e.y);
            float f[8];
            h8_to_f8(vh4[(size_t)e.x * LDH + srcoff + lane], f);
#pragma unroll
            for (int r = 0; r < 8; ++r) acc[r] = fmaf(w, f[r], acc[r]);
        }

        if (MODE == 0) {
            vh4[(size_t)node * LDH + lane] = f8_to_h8(acc);
        } else {
            float4 blo = ((const float4*)bias)[lane * 2];
            float4 bhi = ((const float4*)bias)[lane * 2 + 1];
            float o[8];
            o[0] = fmaxf(acc[0] + blo.x, 0.f);
            o[1] = fmaxf(acc[1] + blo.y, 0.f);
            o[2] = fmaxf(acc[2] + blo.z, 0.f);
            o[3] = fmaxf(acc[3] + blo.w, 0.f);
            o[4] = fmaxf(acc[4] + bhi.x, 0.f);
            o[5] = fmaxf(acc[5] + bhi.y, 0.f);
            o[6] = fmaxf(acc[6] + bhi.z, 0.f);
            o[7] = fmaxf(acc[7] + bhi.w, 0.f);
            if (MODE == 1) {
                ((uint4*)H)[(size_t)node * LPN + lane] = f8_to_h8(o);
            } else {
                int g = batch[node];
                red_add_v4(&g_pool[g * 32 + lane * 8], make_float4(o[0], o[1], o[2], o[3]));
                red_add_v4(&g_pool[g * 32 + lane * 8 + 4], make_float4(o[4], o[5], o[6], o[7]));
            }
        }
    }

    if (MODE == 2) {
        __threadfence();
        __shared__ int is_last;
        if (threadIdx.x == 0)
            is_last = (atomicAdd(&g_done, 1) == (int)gridDim.x - 1);
        __syncthreads();
        if (is_last) {
            __threadfence();
            int t = threadIdx.x;
            if (t < NG * 2) {
                int g = t >> 1;
                int jj = t & 1;
                float cnt = fmaxf(g_cnt[g], 1.0f);
                float s = 0.f;
#pragma unroll
                for (int c = 0; c < 32; ++c) s += g_pool[g * 32 + c] * Wl[c * 2 + jj];
                out[t] = s / cnt + bl[jj];
            }
        }
    }
}

// ---------------- TF32 TC GEMM, hi/lo split, register-prefetch pipeline --------------
// AFP16=0: A fp32, 3-term (hi*bh + hi*bl + al*bh).
// AFP16=1: A fp16 (exactly representable in tf32) -> A_lo == 0, 2-term only.
// grid.y (seg) = 0,1,2: seg 0 writes fp16 Y0h (ld=BN); seg 1/2 write fp16 Vh (ld=2*BN).
template <int BN, int AFP16>
__launch_bounds__(256, 2)
__global__ void gemm_tc_kernel(const void* __restrict__ Avoid,
                               const float* __restrict__ B,
                               int M, int F, int ldn) {
    const int BM = 128, BK = 16;
    const int WARPS_N = BN / 32;
    const int WARPS_M = 8 / WARPS_N;
    const int WM = BM / WARPS_M;
    const int TM = WM / 16;
    const int TN = 4;
    const int BVEC = BK * BN / 4;
    const int BLOADS = (BVEC + 255) / 256;

    __shared__ float As_hi[BM][BK + 4];
    __shared__ float As_lo[AFP16 ? 1 : BM][BK + 4];
    __shared__ float Bs_hi[BK][BN + 4];
    __shared__ float Bs_lo[BK][BN + 4];

    int t = threadIdx.x;
    int warp = t >> 5, lane = t & 31;
    int group = lane >> 2, tg = lane & 3;
    int warp_m = warp % WARPS_M;
    int warp_n = warp / WARPS_M;
    int m_w = warp_m * WM;
    int n_w = warp_n * 32;
    int m0 = blockIdx.x * BM;
    int seg = blockIdx.y;
    int n0 = seg * BN;

    const float*  Af = (const float*)Avoid;
    const __half* Ah = (const __half*)Avoid;

    float acc[TM][TN][4];
#pragma unroll
    for (int i = 0; i < TM; ++i)
#pragma unroll
        for (int j = 0; j < TN; ++j)
#pragma unroll
            for (int r = 0; r < 4; ++r) acc[i][j][r] = 0.f;

    float4 a_pref[2];        // fp32 path
    uint4  a_pref_h;         // fp16 path (8 halfs / thread covers 128x16 tile)
    float4 b_pref[BLOADS];

    // ---- prologue prefetch (k0 = 0)
    if (AFP16) {
        int row = t >> 1, c8 = (t & 1) * 8;
        int m = m0 + row;
        a_pref_h = (m < M) ? *(const uint4*)(Ah + (size_t)m * F + c8)
                           : make_uint4(0u, 0u, 0u, 0u);
    } else {
#pragma unroll
        for (int l = 0; l < 2; ++l) {
            int idx = t + l * 256;
            int row = idx >> 2;
            int c4 = (idx & 3) * 4;
            int m = m0 + row;
            a_pref[l] = (m < M) ? *(const float4*)(Af + (size_t)m * F + c4)
                                : make_float4(0.f, 0.f, 0.f, 0.f);
        }
    }
#pragma unroll
    for (int l = 0; l < BLOADS; ++l) {
        int idx = t + l * 256;
        if (idx < BVEC) {
            int row = idx / (BN / 4);
            int c4 = (idx % (BN / 4)) * 4;
            b_pref[l] = *(const float4*)(B + (size_t)row * ldn + n0 + c4);
        }
    }

    for (int k0 = 0; k0 < F; k0 += BK) {
        // ---- store prefetched A tile to smem
        if (AFP16) {
            int row = t >> 1, c8 = (t & 1) * 8;
            float f[8];
            h8_to_f8(a_pref_h, f);
            *(float4*)&As_hi[row][c8]     = make_float4(f[0], f[1], f[2], f[3]);
            *(float4*)&As_hi[row][c8 + 4] = make_float4(f[4], f[5], f[6], f[7]);
        } else {
#pragma unroll
            for (int l = 0; l < 2; ++l) {
                int idx = t + l * 256;
                int row = idx >> 2;
                int c4 = (idx & 3) * 4;
                float4 v = a_pref[l];
                float hx = tf32_hi(v.x), hy = tf32_hi(v.y), hz = tf32_hi(v.z), hw = tf32_hi(v.w);
                *(float4*)&As_hi[row][c4] = make_float4(hx, hy, hz, hw);
                *(float4*)&As_lo[row][c4] = make_float4(tf32_hi(v.x - hx), tf32_hi(v.y - hy),
                                                        tf32_hi(v.z - hz), tf32_hi(v.w - hw));
            }
        }
#pragma unroll
        for (int l = 0; l < BLOADS; ++l) {
            int idx = t + l * 256;
            if (idx < BVEC) {
                int row = idx / (BN / 4);
                int c4 = (idx % (BN / 4)) * 4;
                float4 v = b_pref[l];
                float hx = tf32_hi(v.x), hy = tf32_hi(v.y), hz = tf32_hi(v.z), hw = tf32_hi(v.w);
                *(float4*)&Bs_hi[row][c4] = make_float4(hx, hy, hz, hw);
                *(float4*)&Bs_lo[row][c4] = make_float4(tf32_hi(v.x - hx), tf32_hi(v.y - hy),
                                                        tf32_hi(v.z - hz), tf32_hi(v.w - hw));
            }
        }
        __syncthreads();

        // ---- prefetch next tile (overlaps with MMA below)
        int kn = k0 + BK;
        if (kn < F) {
            if (AFP16) {
                int row = t >> 1, c8 = (t & 1) * 8;
                int m = m0 + row;
                a_pref_h = (m < M) ? *(const uint4*)(Ah + (size_t)m * F + kn + c8)
                                   : make_uint4(0u, 0u, 0u, 0u);
            } else {
#pragma unroll
                for (int l = 0; l < 2; ++l) {
                    int idx = t + l * 256;
                    int row = idx >> 2;
                    int c4 = (idx & 3) * 4;
                    int m = m0 + row;
                    a_pref[l] = (m < M) ? *(const float4*)(Af + (size_t)m * F + kn + c4)
                                        : make_float4(0.f, 0.f, 0.f, 0.f);
                }
            }
#pragma unroll
            for (int l = 0; l < BLOADS; ++l) {
                int idx = t + l * 256;
                if (idx < BVEC) {
                    int row = idx / (BN / 4);
                    int c4 = (idx % (BN / 4)) * 4;
                    b_pref[l] = *(const float4*)(B + (size_t)(kn + row) * ldn + n0 + c4);
                }
            }
        }

        // ---- compute
#pragma unroll
        for (int ks = 0; ks < 2; ++ks) {
            int kb = ks * 8;
            uint32_t bh[TN][2], bl[TN][2];
#pragma unroll
            for (int j = 0; j < TN; ++j) {
                int n = n_w + j * 8 + group;
                bh[j][0] = __float_as_uint(Bs_hi[kb + tg][n]);
                bh[j][1] = __float_as_uint(Bs_hi[kb + tg + 4][n]);
                bl[j][0] = __float_as_uint(Bs_lo[kb + tg][n]);
                bl[j][1] = __float_as_uint(Bs_lo[kb + tg + 4][n]);
            }
#pragma unroll
            for (int i = 0; i < TM; ++i) {
                int mb = m_w + i * 16;
                uint32_t ah[4];
                ah[0] = __float_as_uint(As_hi[mb + group][kb + tg]);
                ah[1] = __float_as_uint(As_hi[mb + group + 8][kb + tg]);
                ah[2] = __float_as_uint(As_hi[mb + group][kb + tg + 4]);
                ah[3] = __float_as_uint(As_hi[mb + group + 8][kb + tg + 4]);
                if (AFP16) {
#pragma unroll
                    for (int j = 0; j < TN; ++j) {
                        mma_tf32(acc[i][j], ah, bh[j]);
                        mma_tf32(acc[i][j], ah, bl[j]);
                    }
                } else {
                    uint32_t al[4];
                    al[0] = __float_as_uint(As_lo[mb + group][kb + tg]);
                    al[1] = __float_as_uint(As_lo[mb + group + 8][kb + tg]);
                    al[2] = __float_as_uint(As_lo[mb + group][kb + tg + 4]);
                    al[3] = __float_as_uint(As_lo[mb + group + 8][kb + tg + 4]);
#pragma unroll
                    for (int j = 0; j < TN; ++j) {
                        mma_tf32(acc[i][j], ah, bh[j]);
                        mma_tf32(acc[i][j], ah, bl[j]);
                        mma_tf32(acc[i][j], al, bh[j]);
                    }
                }
            }
        }
        __syncthreads();
    }

    // ---- epilogue: all segs write fp16; seg 0 -> Y0h (ld=BN), seg 1/2 -> Vh (ld=2*BN)
#pragma unroll
    for (int i = 0; i < TM; ++i) {
        int mb = m0 + m_w + i * 16;
        int row0 = mb + group;
        int row1 = mb + group + 8;
#pragma unroll
        for (int j = 0; j < TN; ++j) {
            int n = n_w + j * 8 + 2 * tg;
            if (seg == 0) {
                if (row0 < M) {
                    __half2 h = __floats2half2_rn(acc[i][j][0], acc[i][j][1]);
                    *(__half2*)&g_Y0h[(size_t)row0 * BN + n] = h;
                }
                if (row1 < M) {
                    __half2 h = __floats2half2_rn(acc[i][j][2], acc[i][j][3]);
                    *(__half2*)&g_Y0h[(size_t)row1 * BN + n] = h;
                }
            } else {
                int col = (seg - 1) * BN + n;
                if (row0 < M) {
                    __half2 h = __floats2half2_rn(acc[i][j][0], acc[i][j][1]);
                    *(__half2*)&g_Vh[(size_t)row0 * 2 * BN + col] = h;
                }
                if (row1 < M) {
                    __half2 h = __floats2half2_rn(acc[i][j][2], acc[i][j][3]);
                    *(__half2*)&g_Vh[(size_t)row1 * 2 * BN + col] = h;
                }
            }
        }
    }
}

// ---------------- host orchestration (single stream) ----------------
extern "C" void kernel_launch(void* const* d_in, const int* in_sizes, int n_in,
                              void* d_out, int out_size) {
    const float* x     = (const float*)d_in[0];
    const int*   ei    = (const int*)d_in[1];
    const float* ea    = (const float*)d_in[2];
    const int*   batch = (const int*)d_in[3];
    const float* W1    = (const float*)d_in[4];
    const float* b1    = (const float*)d_in[5];
    const float* W2    = (const float*)d_in[6];
    const float* b2    = (const float*)d_in[7];
    const float* W3    = (const float*)d_in[8];
    const float* b3    = (const float*)d_in[9];
    const float* Wl    = (const float*)d_in[10];
    const float* bl    = (const float*)d_in[11];
    const int* src = ei;
    const int* dst = ei + EE;

    __half *pH1h, *pH2h;
    float *pWc1, *pWc2, *pWc3;
    cudaGetSymbolAddress((void**)&pH1h, g_H1h);
    cudaGetSymbolAddress((void**)&pH2h, g_H2h);
    cudaGetSymbolAddress((void**)&pWc1, g_Wc1);
    cudaGetSymbolAddress((void**)&pWc2, g_Wc2);
    cudaGetSymbolAddress((void**)&pWc3, g_Wc3);

    const int T = 256;
    float* outp = (float*)d_out;

    // preamble
    zero_wprep_kernel<<<CDIV(NN, T), T>>>(W1, W2, W3);
    deg_count_kernel<<<CDIV(EE / 4, T), T>>>(src, dst, ea, batch);
    scan_phase1_kernel<<<SCAN_NBLK, 256>>>();
    scan_phase23_kernel<<<SCAN_NBLK, 256>>>();
    scatter_w_kernel<<<CDIV(EE / 4, T), T>>>(src, dst, ea);

    // ---- layer 1: 160 -> 128 (A = x fp32, 3-term) ----
    {
        dim3 grid(CDIV(NN, 128), 3);
        gemm_tc_kernel<128, 0><<<grid, 256>>>(x, pWc1, NN, 160, 384);
    }
    gather_kernel<128, 0><<<CDIV(NN * 16, T), T>>>(nullptr, nullptr, nullptr, nullptr, nullptr, nullptr);
    gather_kernel<128, 1><<<CDIV(NN * 16, T), T>>>(pH1h, b1, nullptr, nullptr, nullptr, nullptr);
    // ---- layer 2: 128 -> 64 (A = H1 fp16, 2-term) ----
    {
        dim3 grid(CDIV(NN, 128), 3);
        gemm_tc_kernel<64, 1><<<grid, 256>>>(pH1h, pWc2, NN, 128, 192);
    }
    gather_kernel<64, 0><<<CDIV(NN * 8, T), T>>>(nullptr, nullptr, nullptr, nullptr, nullptr, nullptr);
    gather_kernel<64, 1><<<CDIV(NN * 8, T), T>>>(pH2h, b2, nullptr, nullptr, nullptr, nullptr);
    // ---- layer 3: 64 -> 32 (A = H2 fp16, 2-term; pool + final linear fused) ----
    {
        dim3 grid(CDIV(NN, 128), 3);
        gemm_tc_kernel<32, 1><<<grid, 256>>>(pH2h, pWc3, NN, 64, 96);
    }
    gather_kernel<32, 0><<<CDIV(NN * 4, T), T>>>(nullptr, nullptr, nullptr, nullptr, nullptr, nullptr);
    gather_kernel<32, 2><<<CDIV(NN * 4, T), T>>>(nullptr, b3, batch, Wl, bl, outp);
}

// round 16
// speedup vs baseline: 1.1096x; 1.0148x over previous
#include <cuda_runtime.h>
#include <cuda_fp16.h>
#include <cstdint>

#define NN 50000
#define EE 500000
#define NG  128

#define CDIV(a,b) (((a)+(b)-1)/(b))
#define SCAN_NBLK CDIV(NN, 256)      // 196

// ---------------- device scratch (no allocation allowed) ----------------
__device__ __align__(16) float  g_dinv[NN];
__device__ __align__(16) __half g_Y0h[NN * 128];    // fp16 Y0 region (max G=128)
__device__ __align__(16) __half g_Vh[NN * 256];     // [V | V2] fp16, ld = 2*G (max 256)
__device__ __align__(16) __half g_H1h[NN * 128];
__device__ __align__(16) __half g_H2h[NN * 64];
__device__ __align__(16) float  g_Wc1[160 * 384];
__device__ __align__(16) float  g_Wc2[128 * 192];
__device__ __align__(16) float  g_Wc3[64 * 96];
__device__ __align__(16) float  g_pool[NG * 32];
__device__ __align__(16) float  g_cnt[NG];
__device__ int   g_done;
// CSR (indexed by dst): packed (src, w-bits)
__device__ int   g_rowptr[NN + 1];
__device__ int   g_fill[NN];
__device__ int   g_bsum[SCAN_NBLK];
__device__ __align__(16) int2  g_csr[EE];

// ---------------- PDL: overlap launch latency with predecessor tail ----------------
__device__ __forceinline__ void pdl_entry() {
#if __CUDA_ARCH__ >= 900
    asm volatile("griddepcontrol.launch_dependents;");
    asm volatile("griddepcontrol.wait;" ::: "memory");
#endif
}

// ---------------- helpers ----------------
__device__ __forceinline__ void red_add_v4(float* addr, float4 v) {
    asm volatile("red.global.add.v4.f32 [%0], {%1,%2,%3,%4};"
                 :: "l"(addr), "f"(v.x), "f"(v.y), "f"(v.z), "f"(v.w)
                 : "memory");
}

__device__ __forceinline__ float tf32_hi(float x) {
    uint32_t u;
    asm("cvt.rna.tf32.f32 %0, %1;" : "=r"(u) : "f"(x));
    return __uint_as_float(u);
}

__device__ __forceinline__ void mma_tf32(float* c, const uint32_t* a, const uint32_t* b) {
    asm volatile("mma.sync.aligned.m16n8k8.row.col.f32.tf32.tf32.f32 "
                 "{%0,%1,%2,%3}, {%4,%5,%6,%7}, {%8,%9}, {%0,%1,%2,%3};"
                 : "+f"(c[0]), "+f"(c[1]), "+f"(c[2]), "+f"(c[3])
                 : "r"(a[0]), "r"(a[1]), "r"(a[2]), "r"(a[3]),
                   "r"(b[0]), "r"(b[1]));
}

// 8 halfs (uint4) -> 8 floats
__device__ __forceinline__ void h8_to_f8(uint4 u, float* f) {
    __half2 a = *(__half2*)&u.x;
    __half2 b = *(__half2*)&u.y;
    __half2 c = *(__half2*)&u.z;
    __half2 d = *(__half2*)&u.w;
    float2 fa = __half22float2(a), fb = __half22float2(b);
    float2 fc = __half22float2(c), fd = __half22float2(d);
    f[0] = fa.x; f[1] = fa.y; f[2] = fb.x; f[3] = fb.y;
    f[4] = fc.x; f[5] = fc.y; f[6] = fd.x; f[7] = fd.y;
}

__device__ __forceinline__ uint4 f8_to_h8(const float* f) {
    __half2 a = __floats2half2_rn(f[0], f[1]);
    __half2 b = __floats2half2_rn(f[2], f[3]);
    __half2 c = __floats2half2_rn(f[4], f[5]);
    __half2 d = __floats2half2_rn(f[6], f[7]);
    uint4 u;
    u.x = *(uint32_t*)&a; u.y = *(uint32_t*)&b;
    u.z = *(uint32_t*)&c; u.w = *(uint32_t*)&d;
    return u;
}

// ---------------- weight prep helper: Wc[f] = [W0-W2 | W1 | 2*W2] ----------------
__device__ __forceinline__ void wprep_one(const float* __restrict__ W, float* __restrict__ Wc,
                                          int F, int G, int t) {
    int f = t / G;
    int c = t - f * G;
    float w0 = W[t];
    float w1 = W[F * G + t];
    float w2 = W[2 * F * G + t];
    Wc[f * 3 * G + c]         = w0 - w2;
    Wc[f * 3 * G + G + c]     = w1;
    Wc[f * 3 * G + 2 * G + c] = 2.f * w2;
}

// ---------------- fused preamble: zero + weight prep ----------------
__global__ void zero_wprep_kernel(const float* __restrict__ W1, const float* __restrict__ W2,
                                  const float* __restrict__ W3) {
    pdl_entry();
    int i = blockIdx.x * blockDim.x + threadIdx.x;
    if (i < NN) { g_dinv[i] = 0.f; g_fill[i] = 0; }
    if (i < NG * 32) g_pool[i] = 0.f;
    if (i < NG) g_cnt[i] = 0.f;
    if (i == 0) g_done = 0;
    const int S1 = 160 * 128, S2 = S1 + 128 * 64, S3 = S2 + 64 * 32;
    if (i < S1)      wprep_one(W1, g_Wc1, 160, 128, i);
    else if (i < S2) wprep_one(W2, g_Wc2, 128, 64, i - S1);
    else if (i < S3) wprep_one(W3, g_Wc3, 64, 32, i - S2);
}

// 4 edges / thread: degree accumulation + CSR row counting + per-graph node counts
__global__ void deg_count_kernel(const int* __restrict__ src, const int* __restrict__ dst,
                                 const float* __restrict__ ea, const int* __restrict__ batch) {
    pdl_entry();
    int t = blockIdx.x * blockDim.x + threadIdx.x;
    if (t < EE / 4) {
        int4  s4 = ((const int4*)src)[t];
        int4  d4 = ((const int4*)dst)[t];
        float4 a4 = ((const float4*)ea)[t];
        atomicAdd(&g_dinv[s4.x], a4.x);
        atomicAdd(&g_dinv[s4.y], a4.y);
        atomicAdd(&g_dinv[s4.z], a4.z);
        atomicAdd(&g_dinv[s4.w], a4.w);
        atomicAdd(&g_fill[d4.x], 1);
        atomicAdd(&g_fill[d4.y], 1);
        atomicAdd(&g_fill[d4.z], 1);
        atomicAdd(&g_fill[d4.w], 1);
    }
    if (t < NN / 4) {
        int4 b4 = ((const int4*)batch)[t];
        atomicAdd(&g_cnt[b4.x], 1.0f);
        atomicAdd(&g_cnt[b4.y], 1.0f);
        atomicAdd(&g_cnt[b4.z], 1.0f);
        atomicAdd(&g_cnt[b4.w], 1.0f);
    }
}

// ---------------- multi-block scan of g_fill -> g_rowptr ----------------
__global__ void scan_phase1_kernel() {
    pdl_entry();
    __shared__ int sh[256];
    int tid = threadIdx.x;
    int i = blockIdx.x * 256 + tid;
    int c = (i < NN) ? g_fill[i] : 0;
    if (i < NN) {
        float d = g_dinv[i];
        g_dinv[i] = (d > 0.f) ? rsqrtf(d) : 0.f;
    }
    int v = c;
    sh[tid] = v;
    __syncthreads();
#pragma unroll
    for (int off = 1; off < 256; off <<= 1) {
        int t = (tid >= off) ? sh[tid - off] : 0;
        __syncthreads();
        v += t;
        sh[tid] = v;
        __syncthreads();
    }
    if (i < NN) g_rowptr[i] = v - c;
    if (tid == 255) g_bsum[blockIdx.x] = sh[255];
}

__global__ void scan_phase23_kernel() {
    pdl_entry();
    __shared__ int sh[256];
    int tid = threadIdx.x;
    int c = (tid < SCAN_NBLK) ? g_bsum[tid] : 0;
    int v = c;
    sh[tid] = v;
    __syncthreads();
#pragma unroll
    for (int off = 1; off < 256; off <<= 1) {
        int t = (tid >= off) ? sh[tid - off] : 0;
        __syncthreads();
        v += t;
        sh[tid] = v;
        __syncthreads();
    }
    int boff = (blockIdx.x > 0) ? sh[blockIdx.x - 1] : 0;
    __syncthreads();
    int i = blockIdx.x * 256 + tid;
    if (i < NN) {
        int r = g_rowptr[i] + boff;
        g_rowptr[i] = r;
        g_fill[i] = r;
    }
    if (i == 0) g_rowptr[NN] = EE;
}

// 4 edges / thread: scatter into packed CSR with normalized weight computed inline
__global__ void scatter_w_kernel(const int* __restrict__ src, const int* __restrict__ dst,
                                 const float* __restrict__ ea) {
    pdl_entry();
    int t = blockIdx.x * blockDim.x + threadIdx.x;
    if (t >= EE / 4) return;
    int4  s4 = ((const int4*)src)[t];
    int4  d4 = ((const int4*)dst)[t];
    float4 a4 = ((const float4*)ea)[t];

    float w0 = -g_dinv[s4.x] * a4.x * g_dinv[d4.x];
    float w1 = -g_dinv[s4.y] * a4.y * g_dinv[d4.y];
    float w2 = -g_dinv[s4.z] * a4.z * g_dinv[d4.z];
    float w3 = -g_dinv[s4.w] * a4.w * g_dinv[d4.w];

    int p0 = atomicAdd(&g_fill[d4.x], 1);
    int p1 = atomicAdd(&g_fill[d4.y], 1);
    int p2 = atomicAdd(&g_fill[d4.z], 1);
    int p3 = atomicAdd(&g_fill[d4.w], 1);

    g_csr[p0] = make_int2(s4.x, __float_as_int(w0));
    g_csr[p1] = make_int2(s4.y, __float_as_int(w1));
    g_csr[p2] = make_int2(s4.z, __float_as_int(w2));
    g_csr[p3] = make_int2(s4.w, __float_as_int(w3));
}

// ---------------- CSR gather propagate (fp16, 16B lanes, packed CSR) ----------------
// MODE 0: Vh.V[n]  = Vh.V[n] + sum_e w * Vh.V2[src]       (Z = V + P V2)
// MODE 1: Hh[n]    = relu(Y0h[n] + sum_e w * Vh.V[src] + b)   (fp16 output)
// MODE 2: pool[batch[n]] += relu(...); last block computes final linear
template <int G, int MODE>
__global__ void gather_kernel(__half* __restrict__ H,
                              const float* __restrict__ bias,
                              const int* __restrict__ batch,
                              const float* __restrict__ Wl,
                              const float* __restrict__ bl,
                              float* __restrict__ out) {
    pdl_entry();
    const int LPN = G / 8;
    const int LDH = G / 4;
    int tid = blockIdx.x * blockDim.x + threadIdx.x;
    int node = tid / LPN;
    int lane = tid % LPN;

    if (node < NN) {
        uint4* vh4 = (uint4*)g_Vh;
        int beg = g_rowptr[node];
        int end = g_rowptr[node + 1];

        const int srcoff = (MODE == 0) ? LPN : 0;
        float acc[8];
        if (MODE == 0) {
            h8_to_f8(vh4[(size_t)node * LDH + lane], acc);
        } else {
            h8_to_f8(((const uint4*)g_Y0h)[(size_t)node * LPN + lane], acc);
        }

        int j = beg;
        for (; j + 3 < end; j += 4) {
            int2 e[4]; uint4 v[4];
#pragma unroll
            for (int u = 0; u < 4; ++u) e[u] = g_csr[j + u];
#pragma unroll
            for (int u = 0; u < 4; ++u) v[u] = vh4[(size_t)e[u].x * LDH + srcoff + lane];
#pragma unroll
            for (int u = 0; u < 4; ++u) {
                float w = __int_as_float(e[u].y);
                float f[8];
                h8_to_f8(v[u], f);
#pragma unroll
                for (int r = 0; r < 8; ++r) acc[r] = fmaf(w, f[r], acc[r]);
            }
        }
        for (; j < end; ++j) {
            int2 e = g_csr[j];
            float w = __int_as_float(e.y);
            float f[8];
            h8_to_f8(vh4[(size_t)e.x * LDH + srcoff + lane], f);
#pragma unroll
            for (int r = 0; r < 8; ++r) acc[r] = fmaf(w, f[r], acc[r]);
        }

        if (MODE == 0) {
            vh4[(size_t)node * LDH + lane] = f8_to_h8(acc);
        } else {
            float4 blo = ((const float4*)bias)[lane * 2];
            float4 bhi = ((const float4*)bias)[lane * 2 + 1];
            float o[8];
            o[0] = fmaxf(acc[0] + blo.x, 0.f);
            o[1] = fmaxf(acc[1] + blo.y, 0.f);
            o[2] = fmaxf(acc[2] + blo.z, 0.f);
            o[3] = fmaxf(acc[3] + blo.w, 0.f);
            o[4] = fmaxf(acc[4] + bhi.x, 0.f);
            o[5] = fmaxf(acc[5] + bhi.y, 0.f);
            o[6] = fmaxf(acc[6] + bhi.z, 0.f);
            o[7] = fmaxf(acc[7] + bhi.w, 0.f);
            if (MODE == 1) {
                ((uint4*)H)[(size_t)node * LPN + lane] = f8_to_h8(o);
            } else {
                int g = batch[node];
                red_add_v4(&g_pool[g * 32 + lane * 8], make_float4(o[0], o[1], o[2], o[3]));
                red_add_v4(&g_pool[g * 32 + lane * 8 + 4], make_float4(o[4], o[5], o[6], o[7]));
            }
        }
    }

    if (MODE == 2) {
        __threadfence();
        __shared__ int is_last;
        if (threadIdx.x == 0)
            is_last = (atomicAdd(&g_done, 1) == (int)gridDim.x - 1);
        __syncthreads();
        if (is_last) {
            __threadfence();
            int t = threadIdx.x;
            if (t < NG * 2) {
                int g = t >> 1;
                int jj = t & 1;
                float cnt = fmaxf(g_cnt[g], 1.0f);
                float s = 0.f;
#pragma unroll
                for (int c = 0; c < 32; ++c) s += g_pool[g * 32 + c] * Wl[c * 2 + jj];
                out[t] = s / cnt + bl[jj];
            }
        }
    }
}

// ---------------- TF32 TC GEMM, hi/lo split, register-prefetch pipeline --------------
// AFP16=0: A fp32, 3-term. AFP16=1: A fp16 (exact in tf32) -> 2-term.
// grid.y (seg) = 0,1,2: seg 0 writes fp16 Y0h (ld=BN); seg 1/2 write fp16 Vh (ld=2*BN).
template <int BN, int AFP16>
__launch_bounds__(256, 2)
__global__ void gemm_tc_kernel(const void* __restrict__ Avoid,
                               const float* __restrict__ B,
                               int M, int F, int ldn) {
    pdl_entry();
    const int BM = 128, BK = 16;
    const int WARPS_N = BN / 32;
    const int WARPS_M = 8 / WARPS_N;
    const int WM = BM / WARPS_M;
    const int TM = WM / 16;
    const int TN = 4;
    const int BVEC = BK * BN / 4;
    const int BLOADS = (BVEC + 255) / 256;

    __shared__ float As_hi[BM][BK + 4];
    __shared__ float As_lo[AFP16 ? 1 : BM][BK + 4];
    __shared__ float Bs_hi[BK][BN + 4];
    __shared__ float Bs_lo[BK][BN + 4];

    int t = threadIdx.x;
    int warp = t >> 5, lane = t & 31;
    int group = lane >> 2, tg = lane & 3;
    int warp_m = warp % WARPS_M;
    int warp_n = warp / WARPS_M;
    int m_w = warp_m * WM;
    int n_w = warp_n * 32;
    int m0 = blockIdx.x * BM;
    int seg = blockIdx.y;
    int n0 = seg * BN;

    const float*  Af = (const float*)Avoid;
    const __half* Ah = (const __half*)Avoid;

    float acc[TM][TN][4];
#pragma unroll
    for (int i = 0; i < TM; ++i)
#pragma unroll
        for (int j = 0; j < TN; ++j)
#pragma unroll
            for (int r = 0; r < 4; ++r) acc[i][j][r] = 0.f;

    float4 a_pref[2];
    uint4  a_pref_h;
    float4 b_pref[BLOADS];

    if (AFP16) {
        int row = t >> 1, c8 = (t & 1) * 8;
        int m = m0 + row;
        a_pref_h = (m < M) ? *(const uint4*)(Ah + (size_t)m * F + c8)
                           : make_uint4(0u, 0u, 0u, 0u);
    } else {
#pragma unroll
        for (int l = 0; l < 2; ++l) {
            int idx = t + l * 256;
            int row = idx >> 2;
            int c4 = (idx & 3) * 4;
            int m = m0 + row;
            a_pref[l] = (m < M) ? *(const float4*)(Af + (size_t)m * F + c4)
                                : make_float4(0.f, 0.f, 0.f, 0.f);
        }
    }
#pragma unroll
    for (int l = 0; l < BLOADS; ++l) {
        int idx = t + l * 256;
        if (idx < BVEC) {
            int row = idx / (BN / 4);
            int c4 = (idx % (BN / 4)) * 4;
            b_pref[l] = *(const float4*)(B + (size_t)row * ldn + n0 + c4);
        }
    }

    for (int k0 = 0; k0 < F; k0 += BK) {
        if (AFP16) {
            int row = t >> 1, c8 = (t & 1) * 8;
            float f[8];
            h8_to_f8(a_pref_h, f);
            *(float4*)&As_hi[row][c8]     = make_float4(f[0], f[1], f[2], f[3]);
            *(float4*)&As_hi[row][c8 + 4] = make_float4(f[4], f[5], f[6], f[7]);
        } else {
#pragma unroll
            for (int l = 0; l < 2; ++l) {
                int idx = t + l * 256;
                int row = idx >> 2;
                int c4 = (idx & 3) * 4;
                float4 v = a_pref[l];
                float hx = tf32_hi(v.x), hy = tf32_hi(v.y), hz = tf32_hi(v.z), hw = tf32_hi(v.w);
                *(float4*)&As_hi[row][c4] = make_float4(hx, hy, hz, hw);
                *(float4*)&As_lo[row][c4] = make_float4(tf32_hi(v.x - hx), tf32_hi(v.y - hy),
                                                        tf32_hi(v.z - hz), tf32_hi(v.w - hw));
            }
        }
#pragma unroll
        for (int l = 0; l < BLOADS; ++l) {
            int idx = t + l * 256;
            if (idx < BVEC) {
                int row = idx / (BN / 4);
                int c4 = (idx % (BN / 4)) * 4;
                float4 v = b_pref[l];
                float hx = tf32_hi(v.x), hy = tf32_hi(v.y), hz = tf32_hi(v.z), hw = tf32_hi(v.w);
                *(float4*)&Bs_hi[row][c4] = make_float4(hx, hy, hz, hw);
                *(float4*)&Bs_lo[row][c4] = make_float4(tf32_hi(v.x - hx), tf32_hi(v.y - hy),
                                                        tf32_hi(v.z - hz), tf32_hi(v.w - hw));
            }
        }
        __syncthreads();

        int kn = k0 + BK;
        if (kn < F) {
            if (AFP16) {
                int row = t >> 1, c8 = (t & 1) * 8;
                int m = m0 + row;
                a_pref_h = (m < M) ? *(const uint4*)(Ah + (size_t)m * F + kn + c8)
                                   : make_uint4(0u, 0u, 0u, 0u);
            } else {
#pragma unroll
                for (int l = 0; l < 2; ++l) {
                    int idx = t + l * 256;
                    int row = idx >> 2;
                    int c4 = (idx & 3) * 4;
                    int m = m0 + row;
                    a_pref[l] = (m < M) ? *(const float4*)(Af + (size_t)m * F + kn + c4)
                                        : make_float4(0.f, 0.f, 0.f, 0.f);
                }
            }
#pragma unroll
            for (int l = 0; l < BLOADS; ++l) {
                int idx = t + l * 256;
                if (idx < BVEC) {
                    int row = idx / (BN / 4);
                    int c4 = (idx % (BN / 4)) * 4;
                    b_pref[l] = *(const float4*)(B + (size_t)(kn + row) * ldn + n0 + c4);
                }
            }
        }

#pragma unroll
        for (int ks = 0; ks < 2; ++ks) {
            int kb = ks * 8;
            uint32_t bh[TN][2], bl[TN][2];
#pragma unroll
            for (int j = 0; j < TN; ++j) {
                int n = n_w + j * 8 + group;
                bh[j][0] = __float_as_uint(Bs_hi[kb + tg][n]);
                bh[j][1] = __float_as_uint(Bs_hi[kb + tg + 4][n]);
                bl[j][0] = __float_as_uint(Bs_lo[kb + tg][n]);
                bl[j][1] = __float_as_uint(Bs_lo[kb + tg + 4][n]);
            }
#pragma unroll
            for (int i = 0; i < TM; ++i) {
                int mb = m_w + i * 16;
                uint32_t ah[4];
                ah[0] = __float_as_uint(As_hi[mb + group][kb + tg]);
                ah[1] = __float_as_uint(As_hi[mb + group + 8][kb + tg]);
                ah[2] = __float_as_uint(As_hi[mb + group][kb + tg + 4]);
                ah[3] = __float_as_uint(As_hi[mb + group + 8][kb + tg + 4]);
                if (AFP16) {
#pragma unroll
                    for (int j = 0; j < TN; ++j) {
                        mma_tf32(acc[i][j], ah, bh[j]);
                        mma_tf32(acc[i][j], ah, bl[j]);
                    }
                } else {
                    uint32_t al[4];
                    al[0] = __float_as_uint(As_lo[mb + group][kb + tg]);
                    al[1] = __float_as_uint(As_lo[mb + group + 8][kb + tg]);
                    al[2] = __float_as_uint(As_lo[mb + group][kb + tg + 4]);
                    al[3] = __float_as_uint(As_lo[mb + group + 8][kb + tg + 4]);
#pragma unroll
                    for (int j = 0; j < TN; ++j) {
                        mma_tf32(acc[i][j], ah, bh[j]);
                        mma_tf32(acc[i][j], ah, bl[j]);
                        mma_tf32(acc[i][j], al, bh[j]);
                    }
                }
            }
        }
        __syncthreads();
    }

#pragma unroll
    for (int i = 0; i < TM; ++i) {
        int mb = m0 + m_w + i * 16;
        int row0 = mb + group;
        int row1 = mb + group + 8;
#pragma unroll
        for (int j = 0; j < TN; ++j) {
            int n = n_w + j * 8 + 2 * tg;
            if (seg == 0) {
                if (row0 < M) {
                    __half2 h = __floats2half2_rn(acc[i][j][0], acc[i][j][1]);
                    *(__half2*)&g_Y0h[(size_t)row0 * BN + n] = h;
                }
                if (row1 < M) {
                    __half2 h = __floats2half2_rn(acc[i][j][2], acc[i][j][3]);
                    *(__half2*)&g_Y0h[(size_t)row1 * BN + n] = h;
                }
            } else {
                int col = (seg - 1) * BN + n;
                if (row0 < M) {
                    __half2 h = __floats2half2_rn(acc[i][j][0], acc[i][j][1]);
                    *(__half2*)&g_Vh[(size_t)row0 * 2 * BN + col] = h;
                }
                if (row1 < M) {
                    __half2 h = __floats2half2_rn(acc[i][j][2], acc[i][j][3]);
                    *(__half2*)&g_Vh[(size_t)row1 * 2 * BN + col] = h;
                }
            }
        }
    }
}

// ---------------- host orchestration (single stream, PDL on every launch) ----------
static inline cudaLaunchConfig_t pdl_cfg(dim3 grid, dim3 block,
                                         cudaLaunchAttribute* attr) {
    attr[0].id = cudaLaunchAttributeProgrammaticStreamSerialization;
    attr[0].val.programmaticStreamSerializationAllowed = 1;
    cudaLaunchConfig_t cfg = {};
    cfg.gridDim = grid;
    cfg.blockDim = block;
    cfg.stream = 0;
    cfg.attrs = attr;
    cfg.numAttrs = 1;
    return cfg;
}

extern "C" void kernel_launch(void* const* d_in, const int* in_sizes, int n_in,
                              void* d_out, int out_size) {
    const float* x     = (const float*)d_in[0];
    const int*   ei    = (const int*)d_in[1];
    const float* ea    = (const float*)d_in[2];
    const int*   batch = (const int*)d_in[3];
    const float* W1    = (const float*)d_in[4];
    const float* b1    = (const float*)d_in[5];
    const float* W2    = (const float*)d_in[6];
    const float* b2    = (const float*)d_in[7];
    const float* W3    = (const float*)d_in[8];
    const float* b3    = (const float*)d_in[9];
    const float* Wl    = (const float*)d_in[10];
    const float* bl    = (const float*)d_in[11];
    const int* src = ei;
    const int* dst = ei + EE;

    __half *pH1h, *pH2h;
    float *pWc1, *pWc2, *pWc3;
    cudaGetSymbolAddress((void**)&pH1h, g_H1h);
    cudaGetSymbolAddress((void**)&pH2h, g_H2h);
    cudaGetSymbolAddress((void**)&pWc1, g_Wc1);
    cudaGetSymbolAddress((void**)&pWc2, g_Wc2);
    cudaGetSymbolAddress((void**)&pWc3, g_Wc3);

    const int T = 256;
    float* outp = (float*)d_out;
    cudaLaunchAttribute attr[1];

    {   // preamble
        cudaLaunchConfig_t c1 = pdl_cfg(CDIV(NN, T), T, attr);
        cudaLaunchKernelEx(&c1, zero_wprep_kernel, W1, W2, W3);
        cudaLaunchConfig_t c2 = pdl_cfg(CDIV(EE / 4, T), T, attr);
        cudaLaunchKernelEx(&c2, deg_count_kernel, src, dst, ea, batch);
        cudaLaunchConfig_t c3 = pdl_cfg(SCAN_NBLK, 256, attr);
        cudaLaunchKernelEx(&c3, scan_phase1_kernel);
        cudaLaunchConfig_t c4 = pdl_cfg(SCAN_NBLK, 256, attr);
        cudaLaunchKernelEx(&c4, scan_phase23_kernel);
        cudaLaunchConfig_t c5 = pdl_cfg(CDIV(EE / 4, T), T, attr);
        cudaLaunchKernelEx(&c5, scatter_w_kernel, src, dst, ea);
    }

    __half* nullh = nullptr;
    const float* nullf = nullptr;
    const int* nulli = nullptr;
    float* nullo = nullptr;

    // ---- layer 1: 160 -> 128 (A = x fp32, 3-term) ----
    {
        cudaLaunchConfig_t cg = pdl_cfg(dim3(CDIV(NN, 128), 3), 256, attr);
        cudaLaunchKernelEx(&cg, gemm_tc_kernel<128, 0>, (const void*)x, (const float*)pWc1,
                           NN, 160, 384);
        cudaLaunchConfig_t c0 = pdl_cfg(CDIV(NN * 16, T), T, attr);
        cudaLaunchKernelEx(&c0, gather_kernel<128, 0>, nullh, nullf, nulli, nullf, nullf, nullo);
        cudaLaunchConfig_t c1 = pdl_cfg(CDIV(NN * 16, T), T, attr);
        cudaLaunchKernelEx(&c1, gather_kernel<128, 1>, pH1h, b1, nulli, nullf, nullf, nullo);
    }
    // ---- layer 2: 128 -> 64 (A = H1 fp16, 2-term) ----
    {
        cudaLaunchConfig_t cg = pdl_cfg(dim3(CDIV(NN, 128), 3), 256, attr);
        cudaLaunchKernelEx(&cg, gemm_tc_kernel<64, 1>, (const void*)pH1h, (const float*)pWc2,
                           NN, 128, 192);
        cudaLaunchConfig_t c0 = pdl_cfg(CDIV(NN * 8, T), T, attr);
        cudaLaunchKernelEx(&c0, gather_kernel<64, 0>, nullh, nullf, nulli, nullf, nullf, nullo);
        cudaLaunchConfig_t c1 = pdl_cfg(CDIV(NN * 8, T), T, attr);
        cudaLaunchKernelEx(&c1, gather_kernel<64, 1>, pH2h, b2, nulli, nullf, nullf, nullo);
    }
    // ---- layer 3: 64 -> 32 (A = H2 fp16, 2-term; pool + final linear fused) ----
    {
        cudaLaunchConfig_t cg = pdl_cfg(dim3(CDIV(NN, 128), 3), 256, attr);
        cudaLaunchKernelEx(&cg, gemm_tc_kernel<32, 1>, (const void*)pH2h, (const float*)pWc3,
                           NN, 64, 96);
        cudaLaunchConfig_t c0 = pdl_cfg(CDIV(NN * 4, T), T, attr);
        cudaLaunchKernelEx(&c0, gather_kernel<32, 0>, nullh, nullf, nulli, nullf, nullf, nullo);
        cudaLaunchConfig_t c1 = pdl_cfg(CDIV(NN * 4, T), T, attr);
        cudaLaunchKernelEx(&c1, gather_kernel<32, 2>, nullh, b3, batch, Wl, bl, outp);
    }
}